// round 6
// baseline (speedup 1.0000x reference)
#include <cuda_runtime.h>
#include <cstdint>

#define DI __device__ __forceinline__

DI void ffma2(unsigned long long& c, unsigned long long a, unsigned long long b){
  asm("fma.rn.f32x2 %0, %1, %2, %0;" : "+l"(c) : "l"(a), "l"(b));
}
DI float2 funpack(unsigned long long v){
  float2 f;
  asm("mov.b64 {%0, %1}, %2;" : "=f"(f.x), "=f"(f.y) : "l"(v));
  return f;
}
DI unsigned long long fdup(float a){
  unsigned long long r;
  asm("mov.b64 %0, {%1, %1};" : "=l"(r) : "f"(a));
  return r;
}
DI void cpa4(uint32_t dst, const float* src, int sz){
  asm volatile("cp.async.ca.shared.global [%0], [%1], 4, %2;"
               :: "r"(dst), "l"(src), "r"(sz) : "memory");
}
DI void cpa_commit(){ asm volatile("cp.async.commit_group;":::"memory"); }
DI void cpa_wait0(){ asm volatile("cp.async.wait_group 0;":::"memory"); }

// ---------------- device scratch (zero-initialized; no allocation) ----------------
__device__ float g_buf1[69222400];   // conv_in out PADDED [8,128,260,260]
__device__ float g_buf2[9469952];    // h1 out PADDED [8,256,68,68]
__device__ float g_buf3[819200];     // h2 out PADDED [8,256,20,20]
__device__ float g_buf4[131072];     // h3 out [8,256,8,8]
__device__ float g_tres[524288];     // residual mid [8,1024,8,8]
__device__ float g_buf5[131072];
__device__ float g_buf6[131072];
__device__ float g_part[4194304];
__device__ float g_embT[131072];
__device__ float g_se[512];
__device__ int   g_idx[512];
__device__ float g_sqn[512];

// =======================================================================
// cp.async implicit-GEMM conv.  BM=BN=128, BK=16, 256 thr, 8x8 split tile.
// A staged via LDG->STS into DUPLICATED smem (no fdup MOVs in mainloop).
// B gathered via cp.async 4B (zero-fill OOB).  Double buffer, 1-tile prefetch.
// MODE 1: split-K partials.  MODE 2: direct padded NCHW write (+bias,+relu).
// PADIN: input is padded [b][IC][IH+4][IW+4] interior at +2 (no bounds).
// =======================================================================
template<int IC,int IH,int IW,int OC,int OH,int OW,
         int KH,int KW,int SH,int SW,int PH,int PW,
         int NSPLIT,int MODE,bool PADIN>
__global__ void __launch_bounds__(256,2)
conv_cpa(const float* __restrict__ W, const float* __restrict__ X,
         const float* __restrict__ bias, float* __restrict__ out)
{
  constexpr int BM=128, BN=128, BK=16;
  constexpr int Ktot=IC*KH*KW, Ksp=Ktot/NSPLIT, NT=Ksp/BK;
  constexpr int OHW=OH*OW, Ntot=8*OHW;
  constexpr int PIH=IH+4, PIW=IW+4;
  static_assert(Ksp%BK==0, "split");

  __shared__ float As2[2][BK][2*BM];   // duplicated A  (32KB)
  __shared__ float Bs[2][BK][BN];      // (16KB) -> total 48KB

  const int tid=threadIdx.x;
  const int n0=blockIdx.x*BN, m0=blockIdx.y*BM, kb0=blockIdx.z*Ksp;

  // A: 2 threads/row, 8 consecutive k each
  const int am=tid>>1, ak=(tid&1)*8;
  const float* Aptr = W + (long)(m0+am)*Ktot + kb0 + ak;

  // B: one k-row, 8 consecutive n per thread
  const int gk=tid>>4, gn=(tid&15)*8;
  int pbase[8], iyv[8], ixv[8];
#pragma unroll
  for(int j=0;j<8;j++){
    int n=n0+gn+j; int b=n/OHW, p=n-b*OHW;
    int oy=p/OW, ox=p-oy*OW;
    int iy=oy*SH-PH, ix=ox*SW-PW;
    if(PADIN){ pbase[j] = b*(IC*PIH*PIW) + (iy+2)*PIW + (ix+2); }
    else     { pbase[j] = b*(IC*IH*IW); iyv[j]=iy; ixv[j]=ix; }
  }
  uint32_t bs0=(uint32_t)__cvta_generic_to_shared(&Bs[0][gk][gn]);
  uint32_t bs1=(uint32_t)__cvta_generic_to_shared(&Bs[1][gk][gn]);

  const int tx4=(tid&15)*4, ty4=(tid>>4)*4;

  unsigned long long acc[8][4];
#pragma unroll
  for(int i=0;i<8;i++){
#pragma unroll
    for(int p=0;p<4;p++) acc[i][p]=0ull;
  }

  auto issueB=[&](int t,int buf){
    int kg=kb0+t*BK+gk;
    int ic=kg/(KH*KW); int r=kg-ic*(KH*KW); int ky=r/KW, kx=r-ky*KW;
    uint32_t dst = buf ? bs1 : bs0;
#pragma unroll
    for(int j=0;j<8;j++){
      if(PADIN){
        cpa4(dst+4u*j, X + pbase[j] + ic*(PIH*PIW) + ky*PIW + kx, 4);
      } else {
        int iy=iyv[j]+ky, ix=ixv[j]+kx;
        bool ok = ((unsigned)iy<(unsigned)IH) & ((unsigned)ix<(unsigned)IW);
        cpa4(dst+4u*j, X + pbase[j] + ic*(IH*IW) + iy*IW + ix, ok?4:0);
      }
    }
    cpa_commit();
  };
  auto stsA=[&](int buf, const float4& x, const float4& y){
    float v[8]={x.x,x.y,x.z,x.w,y.x,y.y,y.z,y.w};
#pragma unroll
    for(int i=0;i<8;i++)
      *(float2*)&As2[buf][ak+i][2*am] = make_float2(v[i],v[i]);
  };

  // prolog: stage tile 0, prefetch A(1)
  float4 a0x=*(const float4*)Aptr, a0y=*(const float4*)(Aptr+4);
  issueB(0,0);
  float4 aNx, aNy;
  if(NT>1){ aNx=*(const float4*)(Aptr+BK); aNy=*(const float4*)(Aptr+BK+4); }
  stsA(0,a0x,a0y);
  cpa_wait0();
  __syncthreads();

#pragma unroll 1
  for(int t=0;t<NT;t++){
    const int cur=t&1, nxt=cur^1;
    if(t+1<NT) issueB(t+1,nxt);
    float4 aFx, aFy;
    if(t+2<NT){ aFx=*(const float4*)(Aptr+(t+2)*BK); aFy=*(const float4*)(Aptr+(t+2)*BK+4); }
#pragma unroll
    for(int k=0;k<BK;k++){
      ulonglong2 A0=*(const ulonglong2*)&As2[cur][k][2*ty4];
      ulonglong2 A1=*(const ulonglong2*)&As2[cur][k][2*ty4+4];
      ulonglong2 A2=*(const ulonglong2*)&As2[cur][k][2*ty4+128];
      ulonglong2 A3=*(const ulonglong2*)&As2[cur][k][2*ty4+132];
      ulonglong2 B0=*(const ulonglong2*)&Bs[cur][k][tx4];
      ulonglong2 B1=*(const ulonglong2*)&Bs[cur][k][tx4+64];
      unsigned long long Ar[8]={A0.x,A0.y,A1.x,A1.y,A2.x,A2.y,A3.x,A3.y};
#pragma unroll
      for(int i=0;i<8;i++){
        ffma2(acc[i][0],Ar[i],B0.x);
        ffma2(acc[i][1],Ar[i],B0.y);
        ffma2(acc[i][2],Ar[i],B1.x);
        ffma2(acc[i][3],Ar[i],B1.y);
      }
    }
    if(t+1<NT){
      stsA(nxt,aNx,aNy);
      aNx=aFx; aNy=aFy;
      cpa_wait0();
    }
    __syncthreads();
  }

  if(MODE==2){
    const int b=n0/OHW; const int pn0=n0-b*OHW;
#pragma unroll
    for(int i=0;i<8;i++){
      int m=m0+ty4+((i<4)?i:(60+i));
      float bv=bias[m];
      const int cols[4]={tx4,tx4+2,tx4+64,tx4+66};
#pragma unroll
      for(int p=0;p<4;p++){
        int nl=pn0+cols[p]; int oy=nl/OW, ox=nl-oy*OW;
        float2 w=funpack(acc[i][p]);
        w.x=fmaxf(w.x+bv,0.f); w.y=fmaxf(w.y+bv,0.f);
        *(float2*)(out + ((long)((b*OC+m)*(OH+4)+(oy+2)))*(OW+4) + ox+2) = w;
      }
    }
  } else {
#pragma unroll
    for(int i=0;i<8;i++){
      int m=m0+ty4+((i<4)?i:(60+i));
      float* pp = out + ((long)blockIdx.z*OC + m)*Ntot + n0;
      float2 v0=funpack(acc[i][0]), v1=funpack(acc[i][1]);
      float2 v2=funpack(acc[i][2]), v3=funpack(acc[i][3]);
      *(float4*)(pp+tx4)    = make_float4(v0.x,v0.y,v1.x,v1.y);
      *(float4*)(pp+tx4+64) = make_float4(v2.x,v2.y,v3.x,v3.y);
    }
  }
}

// ================= old register-staged kernel (small residual layers) =================
template<int IC,int IH,int IW,int OC,int OH,int OW,
         int KH,int KW,int SH,int SW,int PH,int PW,
         int NSPLIT,bool RELU_IN>
__global__ void __launch_bounds__(256,2)
conv_gemm(const float* __restrict__ W, const float* __restrict__ X,
          const float* __restrict__ bias, float* __restrict__ out)
{
  constexpr int BM=128, BN=128, BK=8;
  constexpr int Ktot=IC*KH*KW, Ksp=Ktot/NSPLIT, NT=Ksp/BK;
  constexpr int OHW=OH*OW, Ntot=8*OHW;
  static_assert(Ksp%BK==0,"split");

  __shared__ float As[2][BK][BM];
  __shared__ float Bs[2][BK][BN];

  const int tid=threadIdx.x;
  const int n0=blockIdx.x*BN, m0=blockIdx.y*BM, kb0=blockIdx.z*Ksp;

  const int am=tid>>1, ak=(tid&1)*4;
  const float* Aptr = W + (m0+am)*Ktot + kb0 + ak;

  const int gk=tid>>5, gn=(tid&31)*4;
  int nbase[4], iy0[4], ix0[4];
#pragma unroll
  for(int j=0;j<4;j++){
    int n=n0+gn+j; int b=n/OHW, p=n-b*OHW;
    int oy=p/OW, ox=p-oy*OW;
    iy0[j]=oy*SH-PH; ix0[j]=ox*SW-PW;
    nbase[j]=b*(IC*IH*IW);
  }

  const int tx4=(tid&15)*4, ty4=(tid>>4)*4;

  unsigned long long acc[8][4];
#pragma unroll
  for(int i=0;i<8;i++){
#pragma unroll
    for(int p=0;p<4;p++) acc[i][p]=0ull;
  }

  float4 areg=*(const float4*)Aptr;
  float br[4];
  {
    int kg=kb0+gk;
    int ic=kg/(KH*KW); int r=kg-ic*(KH*KW); int ky=r/KW, kx=r-ky*KW;
#pragma unroll
    for(int j=0;j<4;j++){
      int iy=iy0[j]+ky, ix=ix0[j]+kx;
      float v=0.f;
      if((unsigned)iy<(unsigned)IH && (unsigned)ix<(unsigned)IW)
        v = X[nbase[j]+ic*(IH*IW)+iy*IW+ix];
      if(RELU_IN) v=fmaxf(v,0.f);
      br[j]=v;
    }
  }
  As[0][ak+0][am]=areg.x; As[0][ak+1][am]=areg.y;
  As[0][ak+2][am]=areg.z; As[0][ak+3][am]=areg.w;
  *(float4*)&Bs[0][gk][gn]=make_float4(br[0],br[1],br[2],br[3]);
  __syncthreads();

#pragma unroll 1
  for(int t=0;t<NT;t++){
    const int cur=t&1, nxt=cur^1;
    const bool more=(t+1<NT);
    float4 aN; float bN[4];
    if(more){
      aN=*(const float4*)(Aptr+(t+1)*BK);
      int kg=kb0+(t+1)*BK+gk;
      int ic=kg/(KH*KW); int r=kg-ic*(KH*KW); int ky=r/KW, kx=r-ky*KW;
#pragma unroll
      for(int j=0;j<4;j++){
        int iy=iy0[j]+ky, ix=ix0[j]+kx;
        float v=0.f;
        if((unsigned)iy<(unsigned)IH && (unsigned)ix<(unsigned)IW)
          v = X[nbase[j]+ic*(IH*IW)+iy*IW+ix];
        if(RELU_IN) v=fmaxf(v,0.f);
        bN[j]=v;
      }
    }
#pragma unroll
    for(int k=0;k<BK;k++){
      float4 a0=*(const float4*)&As[cur][k][ty4];
      float4 a1=*(const float4*)&As[cur][k][ty4+64];
      ulonglong2 B0=*(const ulonglong2*)&Bs[cur][k][tx4];
      ulonglong2 B1=*(const ulonglong2*)&Bs[cur][k][tx4+64];
      float av[8]={a0.x,a0.y,a0.z,a0.w,a1.x,a1.y,a1.z,a1.w};
#pragma unroll
      for(int i=0;i<8;i++){
        unsigned long long ad=fdup(av[i]);
        ffma2(acc[i][0],ad,B0.x);
        ffma2(acc[i][1],ad,B0.y);
        ffma2(acc[i][2],ad,B1.x);
        ffma2(acc[i][3],ad,B1.y);
      }
    }
    if(more){
      As[nxt][ak+0][am]=aN.x; As[nxt][ak+1][am]=aN.y;
      As[nxt][ak+2][am]=aN.z; As[nxt][ak+3][am]=aN.w;
      *(float4*)&Bs[nxt][gk][gn]=make_float4(bN[0],bN[1],bN[2],bN[3]);
    }
    __syncthreads();
  }

#pragma unroll
  for(int i=0;i<8;i++){
    int m=m0+ty4+((i<4)?i:(60+i));
    float* pp = out + ((long)blockIdx.z*OC+m)*Ntot + n0;
    float2 v0=funpack(acc[i][0]), v1=funpack(acc[i][1]);
    float2 v2=funpack(acc[i][2]), v3=funpack(acc[i][3]);
    *(float4*)(pp+tx4)    = make_float4(v0.x,v0.y,v1.x,v1.y);
    *(float4*)(pp+tx4+64) = make_float4(v2.x,v2.y,v3.x,v3.y);
  }
}

// ---- split-K reduce + bias + residual-add + relu; optional padded write ----
__global__ void epilogue_k(const float* __restrict__ part, const float* __restrict__ bias,
                           const float* __restrict__ add, float* __restrict__ out,
                           int M, int N, int OHW, int nsplit, int relu,
                           int OWd, int pad)
{
  int gid=blockIdx.x*256+threadIdx.x;
  if(gid>=M*N) return;
  int m=gid/N, n=gid-m*N;
  float s=0.f;
  for(int sp=0; sp<nsplit; sp++) s += part[((long)sp*M+m)*N+n];
  if(bias) s += bias[m];
  int b=n/OHW, p=n-b*OHW;
  if(add) s += add[((long)b*M+m)*OHW+p];
  if(relu) s=fmaxf(s,0.f);
  long oa;
  if(pad){
    int oy=p/OWd, ox=p-oy*OWd;
    int OHd=OHW/OWd;
    oa = ((long)((b*M+m)*(OHd+4)+(oy+2)))*(OWd+4) + ox+2;
  } else {
    oa = ((long)b*M+m)*OHW + p;
  }
  out[oa]=s;
}

// ---- VQ ----
__global__ void transpose_emb_k(const float* __restrict__ emb, float* __restrict__ embT){
  int gid=blockIdx.x*256+threadIdx.x;
  int d=gid>>9, c=gid&511;
  embT[gid]=emb[c*256+d];
}
__global__ void emb_normsT_k(const float* __restrict__ embT, float* __restrict__ se){
  int c=blockIdx.x*256+threadIdx.x;
  float s=0.f;
  for(int d=0; d<256; d++){ float v=embT[d*512+c]; s=fmaf(v,v,s); }
  se[c]=s;
}
__global__ void vq_rows_k(const float* __restrict__ lat, const float* __restrict__ embT,
                          const float* __restrict__ emb, const float* __restrict__ se,
                          int* __restrict__ idxo, float* __restrict__ sqo)
{
  __shared__ float sl[256];
  __shared__ float sval[256];
  __shared__ int   sidx[256];
  int r=blockIdx.x, t=threadIdx.x;
  int b=r>>6, p=r&63;
  sl[t]=lat[((b<<8)+t)*64+p];
  __syncthreads();
  float fn=0.f;
  for(int k=0;k<256;k++) fn=fmaf(sl[k],sl[k],fn);
  float d0=0.f,d1=0.f;
  for(int k=0;k<256;k++){
    float v=sl[k];
    d0=fmaf(embT[k*512+t],     v,d0);
    d1=fmaf(embT[k*512+t+256], v,d1);
  }
  float dist0=fn+se[t]-2.f*d0;
  float dist1=fn+se[t+256]-2.f*d1;
  float best; int bi;
  if(dist1<dist0){best=dist1; bi=t+256;} else {best=dist0; bi=t;}
  sval[t]=best; sidx[t]=bi;
  __syncthreads();
  for(int s=128;s>0;s>>=1){
    if(t<s){
      float v2=sval[t+s]; int i2=sidx[t+s];
      if(v2<sval[t] || (v2==sval[t] && i2<sidx[t])){ sval[t]=v2; sidx[t]=i2; }
    }
    __syncthreads();
  }
  int w=sidx[0];
  if(t==0) idxo[r]=w;
  __syncthreads();
  float diff=emb[w*256+t]-sl[t];
  sval[t]=diff*diff;
  __syncthreads();
  for(int s=128;s>0;s>>=1){
    if(t<s) sval[t]+=sval[t+s];
    __syncthreads();
  }
  if(t==0) sqo[r]=sval[0];
}
__global__ void write_quant_k(const int* __restrict__ idx, const float* __restrict__ emb,
                              float* __restrict__ out){
  int gid=blockIdx.x*256+threadIdx.x;
  int p=gid&63, c=(gid>>6)&255, b=gid>>14;
  out[gid]=emb[idx[(b<<6)+p]*256+c];
}
__global__ void finalize_k(const int* __restrict__ idx, const float* __restrict__ sq,
                           float* __restrict__ out2){
  __shared__ float sh[512];
  __shared__ float ss[512];
  int t=threadIdx.x;
  int cnt=0;
  for(int r=0;r<512;r++) cnt += (idx[r]==t)?1:0;
  float pr=(float)cnt*(1.f/512.f);
  sh[t]=-pr*logf(pr+1e-10f);
  ss[t]=sq[t];
  __syncthreads();
  for(int s=256;s>0;s>>=1){
    if(t<s){ sh[t]+=sh[t+s]; ss[t]+=ss[t+s]; }
    __syncthreads();
  }
  if(t==0){
    out2[0]=2.f*ss[0]*(1.f/131072.f);
    out2[1]=expf(sh[0]);
  }
}

// ---------------- host ----------------
template<int IC,int IH,int IW,int OC,int OH,int OW,int KH,int KW,
         int SH,int SW,int PH,int PW,int NSPLIT,int MODE,bool PADIN>
static void launch_cpa(const float* W, const float* X, const float* bias, float* out){
  dim3 g((8*OH*OW)/128, OC/128, NSPLIT);
  conv_cpa<IC,IH,IW,OC,OH,OW,KH,KW,SH,SW,PH,PW,NSPLIT,MODE,PADIN><<<g,256>>>(W,X,bias,out);
}
template<int IC,int IH,int IW,int OC,int OH,int OW,int KH,int KW,
         int SH,int SW,int PH,int PW,int NSPLIT,bool RIN>
static void launch_old(const float* W, const float* X, const float* bias, float* out){
  dim3 g((8*OH*OW)/128, OC/128, NSPLIT);
  conv_gemm<IC,IH,IW,OC,OH,OW,KH,KW,SH,SW,PH,PW,NSPLIT,RIN><<<g,256>>>(W,X,bias,out);
}

extern "C" void kernel_launch(void* const* d_in, const int* in_sizes, int n_in,
                              void* d_out, int out_size)
{
  const float* x     = (const float*)d_in[0];
  const float* w_in  = (const float*)d_in[1];
  const float* b_in  = (const float*)d_in[2];
  const float* w_h1  = (const float*)d_in[3];
  const float* b_h1  = (const float*)d_in[4];
  const float* w_h2  = (const float*)d_in[5];
  const float* b_h2  = (const float*)d_in[6];
  const float* w_h3  = (const float*)d_in[7];
  const float* b_h3  = (const float*)d_in[8];
  const float* r0_w1 = (const float*)d_in[9];
  const float* r0_w2 = (const float*)d_in[10];
  const float* r1_w1 = (const float*)d_in[11];
  const float* r1_w2 = (const float*)d_in[12];
  const float* emb   = (const float*)d_in[13];
  float* out = (float*)d_out;

  float *b1,*b2,*b3,*b4,*b5,*b6,*tr,*pp,*eT,*se,*sq; int* gi;
  cudaGetSymbolAddress((void**)&b1, g_buf1);
  cudaGetSymbolAddress((void**)&b2, g_buf2);
  cudaGetSymbolAddress((void**)&b3, g_buf3);
  cudaGetSymbolAddress((void**)&b4, g_buf4);
  cudaGetSymbolAddress((void**)&b5, g_buf5);
  cudaGetSymbolAddress((void**)&b6, g_buf6);
  cudaGetSymbolAddress((void**)&tr, g_tres);
  cudaGetSymbolAddress((void**)&pp, g_part);
  cudaGetSymbolAddress((void**)&eT, g_embT);
  cudaGetSymbolAddress((void**)&se, g_se);
  cudaGetSymbolAddress((void**)&sq, g_sqn);
  cudaGetSymbolAddress((void**)&gi, g_idx);

  // launch 0,1 padding; launch 2 conv_in; launch 3 = h1 (profiled slot)
  transpose_emb_k<<<512,256>>>(emb, eT);
  emb_normsT_k<<<2,256>>>(eT, se);
  // conv_in: raw x -> PADDED b1 [8,128,260,260]; bounds-checked gather
  launch_cpa<3,512,512, 128,256,256, 4,4, 2,2, 1,1, 1, 2, false>(w_in, x, b_in, b1);
  // h1 (PROFILED): padded b1 -> PADDED b2 [8,256,68,68]
  launch_cpa<128,256,256, 256,64,64, 7,7, 4,4, 2,2, 1, 2, true>(w_h1, b1, b_h1, b2);
  // h2: padded b2 -> partials; epilogue writes PADDED b3 [8,256,20,20]
  launch_cpa<256,64,64, 256,16,16, 7,7, 4,4, 2,2, 8, 1, true>(w_h2, b2, nullptr, pp);
  epilogue_k<<<(256*2048+255)/256,256>>>(pp, b_h2, nullptr, b3, 256, 2048, 256, 8, 1, 16, 1);
  // h3: padded b3 -> partials; epilogue -> b4 (unpadded)
  launch_cpa<256,16,16, 256,8,8, 3,3, 2,2, 1,1, 16, 1, true>(w_h3, b3, nullptr, pp);
  epilogue_k<<<(256*512+255)/256,256>>>(pp, b_h3, nullptr, b4, 256, 512, 64, 16, 1, 8, 0);

  // residual block 0 (b4 >= 0, relu(h)==h)
  launch_old<256,8,8, 1024,8,8, 1,3, 1,1, 0,1, 8,false>(r0_w1, b4, nullptr, pp);
  epilogue_k<<<(1024*512+255)/256,256>>>(pp, nullptr, nullptr, tr, 1024, 512, 64, 8, 1, 8, 0);
  launch_old<1024,8,8, 256,8,8, 1,1, 1,1, 0,0, 8,false>(r0_w2, tr, nullptr, pp);
  epilogue_k<<<(256*512+255)/256,256>>>(pp, nullptr, b4, b5, 256, 512, 64, 8, 0, 8, 0);

  // residual block 1 (b5 may be negative -> relu on gather)
  launch_old<256,8,8, 1024,8,8, 1,3, 1,1, 0,1, 8,true>(r1_w1, b5, nullptr, pp);
  epilogue_k<<<(1024*512+255)/256,256>>>(pp, nullptr, nullptr, tr, 1024, 512, 64, 8, 1, 8, 0);
  launch_old<1024,8,8, 256,8,8, 1,1, 1,1, 0,0, 8,false>(r1_w2, tr, nullptr, pp);
  epilogue_k<<<(256*512+255)/256,256>>>(pp, nullptr, b5, b6, 256, 512, 64, 8, 1, 8, 0);

  // VQ
  vq_rows_k<<<512,256>>>(b6, eT, emb, se, gi, sq);
  write_quant_k<<<512,256>>>(gi, emb, out);
  finalize_k<<<1,512>>>(gi, sq, out + 131072);
}

// round 9
// speedup vs baseline: 1.4607x; 1.4607x over previous
#include <cuda_runtime.h>
#include <cstdint>

#define DI __device__ __forceinline__

DI void ffma2(unsigned long long& c, unsigned long long a, unsigned long long b){
  asm("fma.rn.f32x2 %0, %1, %2, %0;" : "+l"(c) : "l"(a), "l"(b));
}
DI float2 funpack(unsigned long long v){
  float2 f;
  asm("mov.b64 {%0, %1}, %2;" : "=f"(f.x), "=f"(f.y) : "l"(v));
  return f;
}
DI unsigned long long fdup(float a){
  unsigned long long r;
  asm("mov.b64 %0, {%1, %1};" : "=l"(r) : "f"(a));
  return r;
}

// ---------------- device scratch (zero-initialized; no allocation) ----------------
__device__ float g_buf1[69222400];    // conv_in out PADDED [8,128,260,260]
__device__ float g_buf2[9469952];     // h1 out PADDED [8,256,68,68]
__device__ float g_buf3[524288];      // h2 out [8,256,16,16]
__device__ float g_buf4[131072];      // h3 out [8,256,8,8]
__device__ float g_tres[524288];      // residual mid
__device__ float g_buf5[131072];
__device__ float g_buf6[131072];
__device__ float g_part[4194304];     // split-K partials
__device__ float g_col1[205520896];   // im2col for h1: [6272][32768]  (822MB)
__device__ float g_colS[25690112];    // im2col shared: conv_in [48][524288] then h2 [12544][2048]
__device__ float g_embT[131072];
__device__ float g_se[512];
__device__ int   g_idx[512];
__device__ float g_sqn[512];

// =======================================================================
// Plain GEMM on materialized im2col:  C[m][n] = sum_k A[m][k]*B[k][n]
// A row-major [M][K], B row-major [K][N] (contiguous!).  BM=BN=128, BK=8,
// 256 thr, 8x8 split tile, FFMA2, double-buffered smem.
// MODE 1: split-K partials [z][M][N].
// MODE 2: direct padded NCHW write out[b][m][OH+4][OW+4]@+2, +bias,+relu.
// =======================================================================
template<int Mt,int Nt,int Kt,int NSPLIT,int MODE,int OHt,int OWt>
__global__ void __launch_bounds__(256,2)
gemm_k(const float* __restrict__ A, const float* __restrict__ B,
       const float* __restrict__ bias, float* __restrict__ out)
{
  constexpr int BK=8;
  constexpr int Ksp=Kt/NSPLIT, NT=Ksp/BK;
  constexpr int OHW=OHt*OWt;
  static_assert(Ksp%BK==0,"split");

  __shared__ float As[2][BK][128];
  __shared__ float Bs[2][BK][128];

  const int tid=threadIdx.x;
  const int n0=blockIdx.x*128, m0=blockIdx.y*128, kb=blockIdx.z*Ksp;

  const int am=tid>>1, ak=(tid&1)*4;
  const float* Aptr = A + (long)(m0+am)*Kt + kb + ak;
  const int gk=tid>>5, gn=(tid&31)*4;
  const float* Bptr = B + (long)(kb+gk)*Nt + n0 + gn;

  const int tx4=(tid&15)*4, ty4=(tid>>4)*4;

  unsigned long long acc[8][4];
#pragma unroll
  for(int i=0;i<8;i++){
#pragma unroll
    for(int p=0;p<4;p++) acc[i][p]=0ull;
  }

  float4 areg=*(const float4*)Aptr;
  float4 breg=*(const float4*)Bptr;
  As[0][ak+0][am]=areg.x; As[0][ak+1][am]=areg.y;
  As[0][ak+2][am]=areg.z; As[0][ak+3][am]=areg.w;
  *(float4*)&Bs[0][gk][gn]=breg;
  __syncthreads();

#pragma unroll 1
  for(int t=0;t<NT;t++){
    const int cur=t&1, nxt=cur^1;
    const bool more=(t+1<NT);
    float4 aN, bN;
    if(more){
      aN=*(const float4*)(Aptr+(t+1)*BK);
      bN=*(const float4*)(Bptr+(long)(t+1)*BK*Nt);
    }
#pragma unroll
    for(int k=0;k<BK;k++){
      float4 a0=*(const float4*)&As[cur][k][ty4];
      float4 a1=*(const float4*)&As[cur][k][ty4+64];
      ulonglong2 B0=*(const ulonglong2*)&Bs[cur][k][tx4];
      ulonglong2 B1=*(const ulonglong2*)&Bs[cur][k][tx4+64];
      float av[8]={a0.x,a0.y,a0.z,a0.w,a1.x,a1.y,a1.z,a1.w};
#pragma unroll
      for(int i=0;i<8;i++){
        unsigned long long ad=fdup(av[i]);
        ffma2(acc[i][0],ad,B0.x);
        ffma2(acc[i][1],ad,B0.y);
        ffma2(acc[i][2],ad,B1.x);
        ffma2(acc[i][3],ad,B1.y);
      }
    }
    if(more){
      As[nxt][ak+0][am]=aN.x; As[nxt][ak+1][am]=aN.y;
      As[nxt][ak+2][am]=aN.z; As[nxt][ak+3][am]=aN.w;
      *(float4*)&Bs[nxt][gk][gn]=bN;
    }
    __syncthreads();
  }

  if(MODE==2){
    const int b=n0/OHW; const int pn0=n0-b*OHW;
#pragma unroll
    for(int i=0;i<8;i++){
      int m=m0+ty4+((i<4)?i:(60+i));
      float bv=bias[m];
      const int cols[4]={tx4,tx4+2,tx4+64,tx4+66};
#pragma unroll
      for(int p=0;p<4;p++){
        int nl=pn0+cols[p]; int oy=nl/OWt, ox=nl-oy*OWt;
        float2 w=funpack(acc[i][p]);
        w.x=fmaxf(w.x+bv,0.f); w.y=fmaxf(w.y+bv,0.f);
        *(float2*)(out + ((long)((b*Mt+m)*(OHt+4)+(oy+2)))*(OWt+4) + ox+2) = w;
      }
    }
  } else {
#pragma unroll
    for(int i=0;i<8;i++){
      int m=m0+ty4+((i<4)?i:(60+i));
      float* pp = out + ((long)blockIdx.z*Mt + m)*Nt + n0;
      float2 v0=funpack(acc[i][0]), v1=funpack(acc[i][1]);
      float2 v2=funpack(acc[i][2]), v3=funpack(acc[i][3]);
      *(float4*)(pp+tx4)    = make_float4(v0.x,v0.y,v1.x,v1.y);
      *(float4*)(pp+tx4+64) = make_float4(v2.x,v2.y,v3.x,v3.y);
    }
  }
}

// ---------------- im2col kernels (coalesced read AND write via smem) ----------------
// conv_in: x [8][3][512][512] (unpadded), 4x4 s2 p1 -> col0 [48][524288]
// smem halo offset is +4 so the float4 staging stores stay 16B-aligned.
__global__ void im2col0_k(const float* __restrict__ x, float* __restrict__ col){
  __shared__ float rows[4][520];
  const int tid=threadIdx.x;
  const int blk=blockIdx.x;            // b*256 + oy
  const int b=blk>>8, oy=blk&255;
  for(int ic=0; ic<3; ic++){
    __syncthreads();
    for(int i=tid;i<4*520;i+=256) ((float*)rows)[i]=0.f;
    __syncthreads();
    for(int i=tid;i<4*128;i+=256){
      int ky=i>>7, c=(i&127)*4;
      int iy=2*oy-1+ky;
      if((unsigned)iy<512u)
        *(float4*)&rows[ky][4+c] = *(const float4*)(x + (((long)b*3+ic)*512+iy)*512 + c);
    }
    __syncthreads();
    for(int i=tid;i<16*64;i+=256){
      int kk=i>>6, q=i&63;             // kk=ky*4+kx, ox=4q..4q+3
      int ky=kk>>2, kx=kk&3;
      int s=8*q+kx+3;                  // smem idx for (ox=4q, kx) = 2*ox-1+kx+4
      float4 v=make_float4(rows[ky][s],rows[ky][s+2],rows[ky][s+4],rows[ky][s+6]);
      *(float4*)&col[(long)(ic*16+kk)*524288 + b*65536 + oy*256 + 4*q] = v;
    }
  }
}

// h1: b1 padded [8][128][260][260], 7x7 s4 p2 -> col1 [6272][32768]
__global__ void im2col1_k(const float* __restrict__ b1, float* __restrict__ col){
  __shared__ float rows[7][260];
  const int tid=threadIdx.x;
  const int blk=blockIdx.x;            // b*64 + oy
  const int b=blk>>6, oy=blk&63;
  for(int ic=0; ic<128; ic++){
    __syncthreads();
    const float* src = b1 + (((long)b*128+ic)*260 + 4*oy)*260;  // padded row iy_p=4*oy+ky
    for(int i=tid;i<7*65;i+=256){
      int r=i/65, c=(i-r*65)*4;
      *(float4*)&rows[r][c] = *(const float4*)(src + r*260 + c);
    }
    __syncthreads();
    for(int i=tid;i<49*16;i+=256){
      int kk=i>>4, q=i&15;             // kk=ky*7+kx, ox=4q..4q+3
      int ky=kk/7, kx=kk-ky*7;
      int s=16*q+kx;                   // smem idx = 4*ox + kx (padded coords)
      float4 v=make_float4(rows[ky][s],rows[ky][s+4],rows[ky][s+8],rows[ky][s+12]);
      *(float4*)&col[(long)(ic*49+kk)*32768 + b*4096 + oy*64 + 4*q] = v;
    }
  }
}

// h2: b2 padded [8][256][68][68], 7x7 s4 p2 -> col2 [12544][2048]
__global__ void im2col2_k(const float* __restrict__ b2, float* __restrict__ col){
  __shared__ float rows[7][68];
  const int tid=threadIdx.x;
  const int blk=blockIdx.x;            // b*16 + oy
  const int b=blk>>4, oy=blk&15;
  for(int ic=0; ic<256; ic++){
    __syncthreads();
    const float* src = b2 + (((long)b*256+ic)*68 + 4*oy)*68;
    for(int i=tid;i<7*17;i+=256){
      int r=i/17, c=(i-r*17)*4;
      *(float4*)&rows[r][c] = *(const float4*)(src + r*68 + c);
    }
    __syncthreads();
    for(int i=tid;i<49*4;i+=256){
      int kk=i>>2, q=i&3;
      int ky=kk/7, kx=kk-ky*7;
      int s=16*q+kx;
      float4 v=make_float4(rows[ky][s],rows[ky][s+4],rows[ky][s+8],rows[ky][s+12]);
      *(float4*)&col[(long)(ic*49+kk)*2048 + b*256 + oy*16 + 4*q] = v;
    }
  }
}

// ============ gather-style conv (small residual layers + h3) ============
template<int IC,int IH,int IW,int OC,int OH,int OW,
         int KH,int KW,int SH,int SW,int PH,int PW,
         int NSPLIT,bool RELU_IN>
__global__ void __launch_bounds__(256,2)
conv_gemm(const float* __restrict__ W, const float* __restrict__ X,
          const float* __restrict__ bias, float* __restrict__ out)
{
  constexpr int BM=128, BN=128, BK=8;
  constexpr int Ktot=IC*KH*KW, Ksp=Ktot/NSPLIT, NT=Ksp/BK;
  constexpr int OHW=OH*OW, Ntot=8*OHW;
  static_assert(Ksp%BK==0,"split");

  __shared__ float As[2][BK][BM];
  __shared__ float Bs[2][BK][BN];

  const int tid=threadIdx.x;
  const int n0=blockIdx.x*BN, m0=blockIdx.y*BM, kb0=blockIdx.z*Ksp;

  const int am=tid>>1, ak=(tid&1)*4;
  const float* Aptr = W + (m0+am)*Ktot + kb0 + ak;

  const int gk=tid>>5, gn=(tid&31)*4;
  int nbase[4], iy0[4], ix0[4];
#pragma unroll
  for(int j=0;j<4;j++){
    int n=n0+gn+j; int b=n/OHW, p=n-b*OHW;
    int oy=p/OW, ox=p-oy*OW;
    iy0[j]=oy*SH-PH; ix0[j]=ox*SW-PW;
    nbase[j]=b*(IC*IH*IW);
  }

  const int tx4=(tid&15)*4, ty4=(tid>>4)*4;

  unsigned long long acc[8][4];
#pragma unroll
  for(int i=0;i<8;i++){
#pragma unroll
    for(int p=0;p<4;p++) acc[i][p]=0ull;
  }

  float4 areg=*(const float4*)Aptr;
  float br[4];
  {
    int kg=kb0+gk;
    int ic=kg/(KH*KW); int r=kg-ic*(KH*KW); int ky=r/KW, kx=r-ky*KW;
#pragma unroll
    for(int j=0;j<4;j++){
      int iy=iy0[j]+ky, ix=ix0[j]+kx;
      float v=0.f;
      if((unsigned)iy<(unsigned)IH && (unsigned)ix<(unsigned)IW)
        v = X[nbase[j]+ic*(IH*IW)+iy*IW+ix];
      if(RELU_IN) v=fmaxf(v,0.f);
      br[j]=v;
    }
  }
  As[0][ak+0][am]=areg.x; As[0][ak+1][am]=areg.y;
  As[0][ak+2][am]=areg.z; As[0][ak+3][am]=areg.w;
  *(float4*)&Bs[0][gk][gn]=make_float4(br[0],br[1],br[2],br[3]);
  __syncthreads();

#pragma unroll 1
  for(int t=0;t<NT;t++){
    const int cur=t&1, nxt=cur^1;
    const bool more=(t+1<NT);
    float4 aN; float bN[4];
    if(more){
      aN=*(const float4*)(Aptr+(t+1)*BK);
      int kg=kb0+(t+1)*BK+gk;
      int ic=kg/(KH*KW); int r=kg-ic*(KH*KW); int ky=r/KW, kx=r-ky*KW;
#pragma unroll
      for(int j=0;j<4;j++){
        int iy=iy0[j]+ky, ix=ix0[j]+kx;
        float v=0.f;
        if((unsigned)iy<(unsigned)IH && (unsigned)ix<(unsigned)IW)
          v = X[nbase[j]+ic*(IH*IW)+iy*IW+ix];
        if(RELU_IN) v=fmaxf(v,0.f);
        bN[j]=v;
      }
    }
#pragma unroll
    for(int k=0;k<BK;k++){
      float4 a0=*(const float4*)&As[cur][k][ty4];
      float4 a1=*(const float4*)&As[cur][k][ty4+64];
      ulonglong2 B0=*(const ulonglong2*)&Bs[cur][k][tx4];
      ulonglong2 B1=*(const ulonglong2*)&Bs[cur][k][tx4+64];
      float av[8]={a0.x,a0.y,a0.z,a0.w,a1.x,a1.y,a1.z,a1.w};
#pragma unroll
      for(int i=0;i<8;i++){
        unsigned long long ad=fdup(av[i]);
        ffma2(acc[i][0],ad,B0.x);
        ffma2(acc[i][1],ad,B0.y);
        ffma2(acc[i][2],ad,B1.x);
        ffma2(acc[i][3],ad,B1.y);
      }
    }
    if(more){
      As[nxt][ak+0][am]=aN.x; As[nxt][ak+1][am]=aN.y;
      As[nxt][ak+2][am]=aN.z; As[nxt][ak+3][am]=aN.w;
      *(float4*)&Bs[nxt][gk][gn]=make_float4(bN[0],bN[1],bN[2],bN[3]);
    }
    __syncthreads();
  }

#pragma unroll
  for(int i=0;i<8;i++){
    int m=m0+ty4+((i<4)?i:(60+i));
    float* pp = out + ((long)blockIdx.z*OC+m)*Ntot + n0;
    float2 v0=funpack(acc[i][0]), v1=funpack(acc[i][1]);
    float2 v2=funpack(acc[i][2]), v3=funpack(acc[i][3]);
    *(float4*)(pp+tx4)    = make_float4(v0.x,v0.y,v1.x,v1.y);
    *(float4*)(pp+tx4+64) = make_float4(v2.x,v2.y,v3.x,v3.y);
  }
}

// ---- split-K reduce + bias + residual-add + relu; optional padded write ----
__global__ void epilogue_k(const float* __restrict__ part, const float* __restrict__ bias,
                           const float* __restrict__ add, float* __restrict__ out,
                           int M, int N, int OHW, int nsplit, int relu,
                           int OWd, int pad)
{
  int gid=blockIdx.x*256+threadIdx.x;
  if(gid>=M*N) return;
  int m=gid/N, n=gid-m*N;
  float s=0.f;
  for(int sp=0; sp<nsplit; sp++) s += part[((long)sp*M+m)*N+n];
  if(bias) s += bias[m];
  int b=n/OHW, p=n-b*OHW;
  if(add) s += add[((long)b*M+m)*OHW+p];
  if(relu) s=fmaxf(s,0.f);
  long oa;
  if(pad){
    int oy=p/OWd, ox=p-oy*OWd;
    int OHd=OHW/OWd;
    oa = ((long)((b*M+m)*(OHd+4)+(oy+2)))*(OWd+4) + ox+2;
  } else {
    oa = ((long)b*M+m)*OHW + p;
  }
  out[oa]=s;
}

// ---- VQ ----
__global__ void transpose_emb_k(const float* __restrict__ emb, float* __restrict__ embT){
  int gid=blockIdx.x*256+threadIdx.x;
  int d=gid>>9, c=gid&511;
  embT[gid]=emb[c*256+d];
}
__global__ void emb_normsT_k(const float* __restrict__ embT, float* __restrict__ se){
  int c=blockIdx.x*256+threadIdx.x;
  float s=0.f;
  for(int d=0; d<256; d++){ float v=embT[d*512+c]; s=fmaf(v,v,s); }
  se[c]=s;
}
__global__ void vq_rows_k(const float* __restrict__ lat, const float* __restrict__ embT,
                          const float* __restrict__ emb, const float* __restrict__ se,
                          int* __restrict__ idxo, float* __restrict__ sqo)
{
  __shared__ float sl[256];
  __shared__ float sval[256];
  __shared__ int   sidx[256];
  int r=blockIdx.x, t=threadIdx.x;
  int b=r>>6, p=r&63;
  sl[t]=lat[((b<<8)+t)*64+p];
  __syncthreads();
  float fn=0.f;
  for(int k=0;k<256;k++) fn=fmaf(sl[k],sl[k],fn);
  float d0=0.f,d1=0.f;
  for(int k=0;k<256;k++){
    float v=sl[k];
    d0=fmaf(embT[k*512+t],     v,d0);
    d1=fmaf(embT[k*512+t+256], v,d1);
  }
  float dist0=fn+se[t]-2.f*d0;
  float dist1=fn+se[t+256]-2.f*d1;
  float best; int bi;
  if(dist1<dist0){best=dist1; bi=t+256;} else {best=dist0; bi=t;}
  sval[t]=best; sidx[t]=bi;
  __syncthreads();
  for(int s=128;s>0;s>>=1){
    if(t<s){
      float v2=sval[t+s]; int i2=sidx[t+s];
      if(v2<sval[t] || (v2==sval[t] && i2<sidx[t])){ sval[t]=v2; sidx[t]=i2; }
    }
    __syncthreads();
  }
  int w=sidx[0];
  if(t==0) idxo[r]=w;
  __syncthreads();
  float diff=emb[w*256+t]-sl[t];
  sval[t]=diff*diff;
  __syncthreads();
  for(int s=128;s>0;s>>=1){
    if(t<s) sval[t]+=sval[t+s];
    __syncthreads();
  }
  if(t==0) sqo[r]=sval[0];
}
__global__ void write_quant_k(const int* __restrict__ idx, const float* __restrict__ emb,
                              float* __restrict__ out){
  int gid=blockIdx.x*256+threadIdx.x;
  int p=gid&63, c=(gid>>6)&255, b=gid>>14;
  out[gid]=emb[idx[(b<<6)+p]*256+c];
}
__global__ void finalize_k(const int* __restrict__ idx, const float* __restrict__ sq,
                           float* __restrict__ out2){
  __shared__ float sh[512];
  __shared__ float ss[512];
  int t=threadIdx.x;
  int cnt=0;
  for(int r=0;r<512;r++) cnt += (idx[r]==t)?1:0;
  float pr=(float)cnt*(1.f/512.f);
  sh[t]=-pr*logf(pr+1e-10f);
  ss[t]=sq[t];
  __syncthreads();
  for(int s=256;s>0;s>>=1){
    if(t<s){ sh[t]+=sh[t+s]; ss[t]+=ss[t+s]; }
    __syncthreads();
  }
  if(t==0){
    out2[0]=2.f*ss[0]*(1.f/131072.f);
    out2[1]=expf(sh[0]);
  }
}

// ---------------- host ----------------
template<int IC,int IH,int IW,int OC,int OH,int OW,int KH,int KW,
         int SH,int SW,int PH,int PW,int NSPLIT,bool RIN>
static void launch_old(const float* W, const float* X, const float* bias, float* out){
  dim3 g((8*OH*OW)/128, OC/128, NSPLIT);
  conv_gemm<IC,IH,IW,OC,OH,OW,KH,KW,SH,SW,PH,PW,NSPLIT,RIN><<<g,256>>>(W,X,bias,out);
}

extern "C" void kernel_launch(void* const* d_in, const int* in_sizes, int n_in,
                              void* d_out, int out_size)
{
  const float* x     = (const float*)d_in[0];
  const float* w_in  = (const float*)d_in[1];
  const float* b_in  = (const float*)d_in[2];
  const float* w_h1  = (const float*)d_in[3];
  const float* b_h1  = (const float*)d_in[4];
  const float* w_h2  = (const float*)d_in[5];
  const float* b_h2  = (const float*)d_in[6];
  const float* w_h3  = (const float*)d_in[7];
  const float* b_h3  = (const float*)d_in[8];
  const float* r0_w1 = (const float*)d_in[9];
  const float* r0_w2 = (const float*)d_in[10];
  const float* r1_w1 = (const float*)d_in[11];
  const float* r1_w2 = (const float*)d_in[12];
  const float* emb   = (const float*)d_in[13];
  float* out = (float*)d_out;

  float *b1,*b2,*b3,*b4,*b5,*b6,*tr,*pp,*c1,*cS,*eT,*se,*sq; int* gi;
  cudaGetSymbolAddress((void**)&b1, g_buf1);
  cudaGetSymbolAddress((void**)&b2, g_buf2);
  cudaGetSymbolAddress((void**)&b3, g_buf3);
  cudaGetSymbolAddress((void**)&b4, g_buf4);
  cudaGetSymbolAddress((void**)&b5, g_buf5);
  cudaGetSymbolAddress((void**)&b6, g_buf6);
  cudaGetSymbolAddress((void**)&tr, g_tres);
  cudaGetSymbolAddress((void**)&pp, g_part);
  cudaGetSymbolAddress((void**)&c1, g_col1);
  cudaGetSymbolAddress((void**)&cS, g_colS);
  cudaGetSymbolAddress((void**)&eT, g_embT);
  cudaGetSymbolAddress((void**)&se, g_se);
  cudaGetSymbolAddress((void**)&sq, g_sqn);
  cudaGetSymbolAddress((void**)&gi, g_idx);

  // 0: im2col conv_in
  im2col0_k<<<2048,256>>>(x, cS);
  // 1: conv_in GEMM: [128][48] x [48][524288] -> padded b1, bias+relu
  { dim3 g(4096,1,1); gemm_k<128,524288,48,1,2,256,256><<<g,256>>>(w_in, cS, b_in, b1); }
  // 2: im2col h1
  im2col1_k<<<512,256>>>(b1, c1);
  // 3 (PROFILED): h1 GEMM: [256][6272] x [6272][32768] -> padded b2, bias+relu
  { dim3 g(256,2,1); gemm_k<256,32768,6272,1,2,64,64><<<g,256>>>(w_h1, c1, b_h1, b2); }
  // 4: im2col h2
  im2col2_k<<<128,256>>>(b2, cS);
  // 5: h2 GEMM split-8 -> partials; epilogue -> b3 (unpadded [8,256,16,16])
  { dim3 g(16,2,8); gemm_k<256,2048,12544,8,1,0,0><<<g,256>>>(w_h2, cS, nullptr, pp); }
  epilogue_k<<<(256*2048+255)/256,256>>>(pp, b_h2, nullptr, b3, 256, 2048, 256, 8, 1, 16, 0);
  // h3: gather conv, split-16
  launch_old<256,16,16, 256,8,8, 3,3, 2,2, 1,1, 16,false>(w_h3, b3, nullptr, pp);
  epilogue_k<<<(256*512+255)/256,256>>>(pp, b_h3, nullptr, b4, 256, 512, 64, 16, 1, 8, 0);

  // residual block 0 (b4 >= 0, relu(h)==h)
  launch_old<256,8,8, 1024,8,8, 1,3, 1,1, 0,1, 8,false>(r0_w1, b4, nullptr, pp);
  epilogue_k<<<(1024*512+255)/256,256>>>(pp, nullptr, nullptr, tr, 1024, 512, 64, 8, 1, 8, 0);
  launch_old<1024,8,8, 256,8,8, 1,1, 1,1, 0,0, 8,false>(r0_w2, tr, nullptr, pp);
  epilogue_k<<<(256*512+255)/256,256>>>(pp, nullptr, b4, b5, 256, 512, 64, 8, 0, 8, 0);

  // residual block 1 (b5 may be negative -> relu on gather)
  launch_old<256,8,8, 1024,8,8, 1,3, 1,1, 0,1, 8,true>(r1_w1, b5, nullptr, pp);
  epilogue_k<<<(1024*512+255)/256,256>>>(pp, nullptr, nullptr, tr, 1024, 512, 64, 8, 1, 8, 0);
  launch_old<1024,8,8, 256,8,8, 1,1, 1,1, 0,0, 8,false>(r1_w2, tr, nullptr, pp);
  epilogue_k<<<(256*512+255)/256,256>>>(pp, nullptr, b5, b6, 256, 512, 64, 8, 1, 8, 0);

  // VQ
  transpose_emb_k<<<512,256>>>(emb, eT);
  emb_normsT_k<<<2,256>>>(eT, se);
  vq_rows_k<<<512,256>>>(b6, eT, emb, se, gi, sq);
  write_quant_k<<<512,256>>>(gi, emb, out);
  finalize_k<<<1,512>>>(gi, sq, out + 131072);
}

// round 10
// speedup vs baseline: 1.4645x; 1.0026x over previous
#include <cuda_runtime.h>
#include <cstdint>

#define DI __device__ __forceinline__

DI void ffma2(unsigned long long& c, unsigned long long a, unsigned long long b){
  asm("fma.rn.f32x2 %0, %1, %2, %0;" : "+l"(c) : "l"(a), "l"(b));
}
DI float2 funpack(unsigned long long v){
  float2 f;
  asm("mov.b64 {%0, %1}, %2;" : "=f"(f.x), "=f"(f.y) : "l"(v));
  return f;
}
DI unsigned long long fdup(float a){
  unsigned long long r;
  asm("mov.b64 %0, {%1, %1};" : "=l"(r) : "f"(a));
  return r;
}

// ---------------- device scratch (zero-initialized; no allocation) ----------------
__device__ float g_buf1[69222400];    // conv_in out PADDED [8,128,260,260]
__device__ float g_buf2[9469952];     // h1 out PADDED [8,256,68,68]
__device__ float g_buf3[524288];      // h2 out [8,256,16,16]
__device__ float g_buf4[131072];      // h3 out [8,256,8,8]
__device__ float g_tres[524288];      // residual mid
__device__ float g_buf5[131072];
__device__ float g_buf6[131072];
__device__ float g_part[4194304];     // split-K partials
__device__ float g_col1[205520896];   // im2col for h1: [6272][32768]  (822MB)
__device__ float g_colS[25690112];    // im2col shared: conv_in [48][524288] then h2 [12544][2048]
__device__ float g_embT[131072];
__device__ float g_se[512];
__device__ int   g_idx[512];
__device__ float g_sqn[512];

// =======================================================================
// Plain GEMM on materialized im2col:  C[m][n] = sum_k A[m][k]*B[k][n]
// A row-major [M][K], B row-major [K][N] (contiguous!).  BM=BN=128, BK=8,
// 256 thr, 8x8 split tile, FFMA2, double-buffered smem.
// MODE 1: split-K partials [z][M][N].
// MODE 2: direct padded NCHW write out[b][m][OH+4][OW+4]@+2, +bias,+relu.
// =======================================================================
template<int Mt,int Nt,int Kt,int NSPLIT,int MODE,int OHt,int OWt>
__global__ void __launch_bounds__(256,2)
gemm_k(const float* __restrict__ A, const float* __restrict__ B,
       const float* __restrict__ bias, float* __restrict__ out)
{
  constexpr int BK=8;
  constexpr int Ksp=Kt/NSPLIT, NT=Ksp/BK;
  constexpr int OHW=OHt*OWt;
  static_assert(Ksp%BK==0,"split");

  __shared__ float As[2][BK][128];
  __shared__ float Bs[2][BK][128];

  const int tid=threadIdx.x;
  const int n0=blockIdx.x*128, m0=blockIdx.y*128, kb=blockIdx.z*Ksp;

  const int am=tid>>1, ak=(tid&1)*4;
  const float* Aptr = A + (long)(m0+am)*Kt + kb + ak;
  const int gk=tid>>5, gn=(tid&31)*4;
  const float* Bptr = B + (long)(kb+gk)*Nt + n0 + gn;

  const int tx4=(tid&15)*4, ty4=(tid>>4)*4;

  unsigned long long acc[8][4];
#pragma unroll
  for(int i=0;i<8;i++){
#pragma unroll
    for(int p=0;p<4;p++) acc[i][p]=0ull;
  }

  float4 areg=*(const float4*)Aptr;
  float4 breg=*(const float4*)Bptr;
  As[0][ak+0][am]=areg.x; As[0][ak+1][am]=areg.y;
  As[0][ak+2][am]=areg.z; As[0][ak+3][am]=areg.w;
  *(float4*)&Bs[0][gk][gn]=breg;
  __syncthreads();

#pragma unroll 1
  for(int t=0;t<NT;t++){
    const int cur=t&1, nxt=cur^1;
    const bool more=(t+1<NT);
    float4 aN, bN;
    if(more){
      aN=*(const float4*)(Aptr+(t+1)*BK);
      bN=*(const float4*)(Bptr+(long)(t+1)*BK*Nt);
    }
#pragma unroll
    for(int k=0;k<BK;k++){
      float4 a0=*(const float4*)&As[cur][k][ty4];
      float4 a1=*(const float4*)&As[cur][k][ty4+64];
      ulonglong2 B0=*(const ulonglong2*)&Bs[cur][k][tx4];
      ulonglong2 B1=*(const ulonglong2*)&Bs[cur][k][tx4+64];
      float av[8]={a0.x,a0.y,a0.z,a0.w,a1.x,a1.y,a1.z,a1.w};
#pragma unroll
      for(int i=0;i<8;i++){
        unsigned long long ad=fdup(av[i]);
        ffma2(acc[i][0],ad,B0.x);
        ffma2(acc[i][1],ad,B0.y);
        ffma2(acc[i][2],ad,B1.x);
        ffma2(acc[i][3],ad,B1.y);
      }
    }
    if(more){
      As[nxt][ak+0][am]=aN.x; As[nxt][ak+1][am]=aN.y;
      As[nxt][ak+2][am]=aN.z; As[nxt][ak+3][am]=aN.w;
      *(float4*)&Bs[nxt][gk][gn]=bN;
    }
    __syncthreads();
  }

  if(MODE==2){
    const int b=n0/OHW; const int pn0=n0-b*OHW;
#pragma unroll
    for(int i=0;i<8;i++){
      int m=m0+ty4+((i<4)?i:(60+i));
      float bv=bias[m];
      const int cols[4]={tx4,tx4+2,tx4+64,tx4+66};
#pragma unroll
      for(int p=0;p<4;p++){
        int nl=pn0+cols[p]; int oy=nl/OWt, ox=nl-oy*OWt;
        float2 w=funpack(acc[i][p]);
        w.x=fmaxf(w.x+bv,0.f); w.y=fmaxf(w.y+bv,0.f);
        *(float2*)(out + ((long)((b*Mt+m)*(OHt+4)+(oy+2)))*(OWt+4) + ox+2) = w;
      }
    }
  } else {
#pragma unroll
    for(int i=0;i<8;i++){
      int m=m0+ty4+((i<4)?i:(60+i));
      float* pp = out + ((long)blockIdx.z*Mt + m)*Nt + n0;
      float2 v0=funpack(acc[i][0]), v1=funpack(acc[i][1]);
      float2 v2=funpack(acc[i][2]), v3=funpack(acc[i][3]);
      *(float4*)(pp+tx4)    = make_float4(v0.x,v0.y,v1.x,v1.y);
      *(float4*)(pp+tx4+64) = make_float4(v2.x,v2.y,v3.x,v3.y);
    }
  }
}

// ---------------- im2col kernels (coalesced read AND write via smem) ----------------
// conv_in: x [8][3][512][512] (unpadded), 4x4 s2 p1 -> col0 [48][524288]
// smem halo offset is +4 so the float4 staging stores stay 16B-aligned.
__global__ void im2col0_k(const float* __restrict__ x, float* __restrict__ col){
  __shared__ float rows[4][520];
  const int tid=threadIdx.x;
  const int blk=blockIdx.x;            // b*256 + oy
  const int b=blk>>8, oy=blk&255;
  for(int ic=0; ic<3; ic++){
    __syncthreads();
    for(int i=tid;i<4*520;i+=256) ((float*)rows)[i]=0.f;
    __syncthreads();
    for(int i=tid;i<4*128;i+=256){
      int ky=i>>7, c=(i&127)*4;
      int iy=2*oy-1+ky;
      if((unsigned)iy<512u)
        *(float4*)&rows[ky][4+c] = *(const float4*)(x + (((long)b*3+ic)*512+iy)*512 + c);
    }
    __syncthreads();
    for(int i=tid;i<16*64;i+=256){
      int kk=i>>6, q=i&63;             // kk=ky*4+kx, ox=4q..4q+3
      int ky=kk>>2, kx=kk&3;
      int s=8*q+kx+3;                  // smem idx for (ox=4q, kx) = 2*ox-1+kx+4
      float4 v=make_float4(rows[ky][s],rows[ky][s+2],rows[ky][s+4],rows[ky][s+6]);
      *(float4*)&col[(long)(ic*16+kk)*524288 + b*65536 + oy*256 + 4*q] = v;
    }
  }
}

// h1: b1 padded [8][128][260][260], 7x7 s4 p2 -> col1 [6272][32768]
__global__ void im2col1_k(const float* __restrict__ b1, float* __restrict__ col){
  __shared__ float rows[7][260];
  const int tid=threadIdx.x;
  const int blk=blockIdx.x;            // b*64 + oy
  const int b=blk>>6, oy=blk&63;
  for(int ic=0; ic<128; ic++){
    __syncthreads();
    const float* src = b1 + (((long)b*128+ic)*260 + 4*oy)*260;  // padded row iy_p=4*oy+ky
    for(int i=tid;i<7*65;i+=256){
      int r=i/65, c=(i-r*65)*4;
      *(float4*)&rows[r][c] = *(const float4*)(src + r*260 + c);
    }
    __syncthreads();
    for(int i=tid;i<49*16;i+=256){
      int kk=i>>4, q=i&15;             // kk=ky*7+kx, ox=4q..4q+3
      int ky=kk/7, kx=kk-ky*7;
      int s=16*q+kx;                   // smem idx = 4*ox + kx (padded coords)
      float4 v=make_float4(rows[ky][s],rows[ky][s+4],rows[ky][s+8],rows[ky][s+12]);
      *(float4*)&col[(long)(ic*49+kk)*32768 + b*4096 + oy*64 + 4*q] = v;
    }
  }
}

// h2: b2 padded [8][256][68][68], 7x7 s4 p2 -> col2 [12544][2048]
__global__ void im2col2_k(const float* __restrict__ b2, float* __restrict__ col){
  __shared__ float rows[7][68];
  const int tid=threadIdx.x;
  const int blk=blockIdx.x;            // b*16 + oy
  const int b=blk>>4, oy=blk&15;
  for(int ic=0; ic<256; ic++){
    __syncthreads();
    const float* src = b2 + (((long)b*256+ic)*68 + 4*oy)*68;
    for(int i=tid;i<7*17;i+=256){
      int r=i/17, c=(i-r*17)*4;
      *(float4*)&rows[r][c] = *(const float4*)(src + r*68 + c);
    }
    __syncthreads();
    for(int i=tid;i<49*4;i+=256){
      int kk=i>>2, q=i&3;
      int ky=kk/7, kx=kk-ky*7;
      int s=16*q+kx;
      float4 v=make_float4(rows[ky][s],rows[ky][s+4],rows[ky][s+8],rows[ky][s+12]);
      *(float4*)&col[(long)(ic*49+kk)*2048 + b*256 + oy*16 + 4*q] = v;
    }
  }
}

// ============ gather-style conv (small residual layers + h3) ============
template<int IC,int IH,int IW,int OC,int OH,int OW,
         int KH,int KW,int SH,int SW,int PH,int PW,
         int NSPLIT,bool RELU_IN>
__global__ void __launch_bounds__(256,2)
conv_gemm(const float* __restrict__ W, const float* __restrict__ X,
          const float* __restrict__ bias, float* __restrict__ out)
{
  constexpr int BM=128, BN=128, BK=8;
  constexpr int Ktot=IC*KH*KW, Ksp=Ktot/NSPLIT, NT=Ksp/BK;
  constexpr int OHW=OH*OW, Ntot=8*OHW;
  static_assert(Ksp%BK==0,"split");

  __shared__ float As[2][BK][BM];
  __shared__ float Bs[2][BK][BN];

  const int tid=threadIdx.x;
  const int n0=blockIdx.x*BN, m0=blockIdx.y*BM, kb0=blockIdx.z*Ksp;

  const int am=tid>>1, ak=(tid&1)*4;
  const float* Aptr = W + (m0+am)*Ktot + kb0 + ak;

  const int gk=tid>>5, gn=(tid&31)*4;
  int nbase[4], iy0[4], ix0[4];
#pragma unroll
  for(int j=0;j<4;j++){
    int n=n0+gn+j; int b=n/OHW, p=n-b*OHW;
    int oy=p/OW, ox=p-oy*OW;
    iy0[j]=oy*SH-PH; ix0[j]=ox*SW-PW;
    nbase[j]=b*(IC*IH*IW);
  }

  const int tx4=(tid&15)*4, ty4=(tid>>4)*4;

  unsigned long long acc[8][4];
#pragma unroll
  for(int i=0;i<8;i++){
#pragma unroll
    for(int p=0;p<4;p++) acc[i][p]=0ull;
  }

  float4 areg=*(const float4*)Aptr;
  float br[4];
  {
    int kg=kb0+gk;
    int ic=kg/(KH*KW); int r=kg-ic*(KH*KW); int ky=r/KW, kx=r-ky*KW;
#pragma unroll
    for(int j=0;j<4;j++){
      int iy=iy0[j]+ky, ix=ix0[j]+kx;
      float v=0.f;
      if((unsigned)iy<(unsigned)IH && (unsigned)ix<(unsigned)IW)
        v = X[nbase[j]+ic*(IH*IW)+iy*IW+ix];
      if(RELU_IN) v=fmaxf(v,0.f);
      br[j]=v;
    }
  }
  As[0][ak+0][am]=areg.x; As[0][ak+1][am]=areg.y;
  As[0][ak+2][am]=areg.z; As[0][ak+3][am]=areg.w;
  *(float4*)&Bs[0][gk][gn]=make_float4(br[0],br[1],br[2],br[3]);
  __syncthreads();

#pragma unroll 1
  for(int t=0;t<NT;t++){
    const int cur=t&1, nxt=cur^1;
    const bool more=(t+1<NT);
    float4 aN; float bN[4];
    if(more){
      aN=*(const float4*)(Aptr+(t+1)*BK);
      int kg=kb0+(t+1)*BK+gk;
      int ic=kg/(KH*KW); int r=kg-ic*(KH*KW); int ky=r/KW, kx=r-ky*KW;
#pragma unroll
      for(int j=0;j<4;j++){
        int iy=iy0[j]+ky, ix=ix0[j]+kx;
        float v=0.f;
        if((unsigned)iy<(unsigned)IH && (unsigned)ix<(unsigned)IW)
          v = X[nbase[j]+ic*(IH*IW)+iy*IW+ix];
        if(RELU_IN) v=fmaxf(v,0.f);
        bN[j]=v;
      }
    }
#pragma unroll
    for(int k=0;k<BK;k++){
      float4 a0=*(const float4*)&As[cur][k][ty4];
      float4 a1=*(const float4*)&As[cur][k][ty4+64];
      ulonglong2 B0=*(const ulonglong2*)&Bs[cur][k][tx4];
      ulonglong2 B1=*(const ulonglong2*)&Bs[cur][k][tx4+64];
      float av[8]={a0.x,a0.y,a0.z,a0.w,a1.x,a1.y,a1.z,a1.w};
#pragma unroll
      for(int i=0;i<8;i++){
        unsigned long long ad=fdup(av[i]);
        ffma2(acc[i][0],ad,B0.x);
        ffma2(acc[i][1],ad,B0.y);
        ffma2(acc[i][2],ad,B1.x);
        ffma2(acc[i][3],ad,B1.y);
      }
    }
    if(more){
      As[nxt][ak+0][am]=aN.x; As[nxt][ak+1][am]=aN.y;
      As[nxt][ak+2][am]=aN.z; As[nxt][ak+3][am]=aN.w;
      *(float4*)&Bs[nxt][gk][gn]=make_float4(bN[0],bN[1],bN[2],bN[3]);
    }
    __syncthreads();
  }

#pragma unroll
  for(int i=0;i<8;i++){
    int m=m0+ty4+((i<4)?i:(60+i));
    float* pp = out + ((long)blockIdx.z*OC+m)*Ntot + n0;
    float2 v0=funpack(acc[i][0]), v1=funpack(acc[i][1]);
    float2 v2=funpack(acc[i][2]), v3=funpack(acc[i][3]);
    *(float4*)(pp+tx4)    = make_float4(v0.x,v0.y,v1.x,v1.y);
    *(float4*)(pp+tx4+64) = make_float4(v2.x,v2.y,v3.x,v3.y);
  }
}

// ---- split-K reduce + bias + residual-add + relu; optional padded write ----
__global__ void epilogue_k(const float* __restrict__ part, const float* __restrict__ bias,
                           const float* __restrict__ add, float* __restrict__ out,
                           int M, int N, int OHW, int nsplit, int relu,
                           int OWd, int pad)
{
  int gid=blockIdx.x*256+threadIdx.x;
  if(gid>=M*N) return;
  int m=gid/N, n=gid-m*N;
  float s=0.f;
  for(int sp=0; sp<nsplit; sp++) s += part[((long)sp*M+m)*N+n];
  if(bias) s += bias[m];
  int b=n/OHW, p=n-b*OHW;
  if(add) s += add[((long)b*M+m)*OHW+p];
  if(relu) s=fmaxf(s,0.f);
  long oa;
  if(pad){
    int oy=p/OWd, ox=p-oy*OWd;
    int OHd=OHW/OWd;
    oa = ((long)((b*M+m)*(OHd+4)+(oy+2)))*(OWd+4) + ox+2;
  } else {
    oa = ((long)b*M+m)*OHW + p;
  }
  out[oa]=s;
}

// ---- VQ ----
__global__ void transpose_emb_k(const float* __restrict__ emb, float* __restrict__ embT){
  int gid=blockIdx.x*256+threadIdx.x;
  int d=gid>>9, c=gid&511;
  embT[gid]=emb[c*256+d];
}
__global__ void emb_normsT_k(const float* __restrict__ embT, float* __restrict__ se){
  int c=blockIdx.x*256+threadIdx.x;
  float s=0.f;
  for(int d=0; d<256; d++){ float v=embT[d*512+c]; s=fmaf(v,v,s); }
  se[c]=s;
}
__global__ void vq_rows_k(const float* __restrict__ lat, const float* __restrict__ embT,
                          const float* __restrict__ emb, const float* __restrict__ se,
                          int* __restrict__ idxo, float* __restrict__ sqo)
{
  __shared__ float sl[256];
  __shared__ float sval[256];
  __shared__ int   sidx[256];
  int r=blockIdx.x, t=threadIdx.x;
  int b=r>>6, p=r&63;
  sl[t]=lat[((b<<8)+t)*64+p];
  __syncthreads();
  float fn=0.f;
  for(int k=0;k<256;k++) fn=fmaf(sl[k],sl[k],fn);
  float d0=0.f,d1=0.f;
  for(int k=0;k<256;k++){
    float v=sl[k];
    d0=fmaf(embT[k*512+t],     v,d0);
    d1=fmaf(embT[k*512+t+256], v,d1);
  }
  float dist0=fn+se[t]-2.f*d0;
  float dist1=fn+se[t+256]-2.f*d1;
  float best; int bi;
  if(dist1<dist0){best=dist1; bi=t+256;} else {best=dist0; bi=t;}
  sval[t]=best; sidx[t]=bi;
  __syncthreads();
  for(int s=128;s>0;s>>=1){
    if(t<s){
      float v2=sval[t+s]; int i2=sidx[t+s];
      if(v2<sval[t] || (v2==sval[t] && i2<sidx[t])){ sval[t]=v2; sidx[t]=i2; }
    }
    __syncthreads();
  }
  int w=sidx[0];
  if(t==0) idxo[r]=w;
  __syncthreads();
  float diff=emb[w*256+t]-sl[t];
  sval[t]=diff*diff;
  __syncthreads();
  for(int s=128;s>0;s>>=1){
    if(t<s) sval[t]+=sval[t+s];
    __syncthreads();
  }
  if(t==0) sqo[r]=sval[0];
}
__global__ void write_quant_k(const int* __restrict__ idx, const float* __restrict__ emb,
                              float* __restrict__ out){
  int gid=blockIdx.x*256+threadIdx.x;
  int p=gid&63, c=(gid>>6)&255, b=gid>>14;
  out[gid]=emb[idx[(b<<6)+p]*256+c];
}
__global__ void finalize_k(const int* __restrict__ idx, const float* __restrict__ sq,
                           float* __restrict__ out2){
  __shared__ float sh[512];
  __shared__ float ss[512];
  int t=threadIdx.x;
  int cnt=0;
  for(int r=0;r<512;r++) cnt += (idx[r]==t)?1:0;
  float pr=(float)cnt*(1.f/512.f);
  sh[t]=-pr*logf(pr+1e-10f);
  ss[t]=sq[t];
  __syncthreads();
  for(int s=256;s>0;s>>=1){
    if(t<s){ sh[t]+=sh[t+s]; ss[t]+=ss[t+s]; }
    __syncthreads();
  }
  if(t==0){
    out2[0]=2.f*ss[0]*(1.f/131072.f);
    out2[1]=expf(sh[0]);
  }
}

// ---------------- host ----------------
template<int IC,int IH,int IW,int OC,int OH,int OW,int KH,int KW,
         int SH,int SW,int PH,int PW,int NSPLIT,bool RIN>
static void launch_old(const float* W, const float* X, const float* bias, float* out){
  dim3 g((8*OH*OW)/128, OC/128, NSPLIT);
  conv_gemm<IC,IH,IW,OC,OH,OW,KH,KW,SH,SW,PH,PW,NSPLIT,RIN><<<g,256>>>(W,X,bias,out);
}

extern "C" void kernel_launch(void* const* d_in, const int* in_sizes, int n_in,
                              void* d_out, int out_size)
{
  const float* x     = (const float*)d_in[0];
  const float* w_in  = (const float*)d_in[1];
  const float* b_in  = (const float*)d_in[2];
  const float* w_h1  = (const float*)d_in[3];
  const float* b_h1  = (const float*)d_in[4];
  const float* w_h2  = (const float*)d_in[5];
  const float* b_h2  = (const float*)d_in[6];
  const float* w_h3  = (const float*)d_in[7];
  const float* b_h3  = (const float*)d_in[8];
  const float* r0_w1 = (const float*)d_in[9];
  const float* r0_w2 = (const float*)d_in[10];
  const float* r1_w1 = (const float*)d_in[11];
  const float* r1_w2 = (const float*)d_in[12];
  const float* emb   = (const float*)d_in[13];
  float* out = (float*)d_out;

  float *b1,*b2,*b3,*b4,*b5,*b6,*tr,*pp,*c1,*cS,*eT,*se,*sq; int* gi;
  cudaGetSymbolAddress((void**)&b1, g_buf1);
  cudaGetSymbolAddress((void**)&b2, g_buf2);
  cudaGetSymbolAddress((void**)&b3, g_buf3);
  cudaGetSymbolAddress((void**)&b4, g_buf4);
  cudaGetSymbolAddress((void**)&b5, g_buf5);
  cudaGetSymbolAddress((void**)&b6, g_buf6);
  cudaGetSymbolAddress((void**)&tr, g_tres);
  cudaGetSymbolAddress((void**)&pp, g_part);
  cudaGetSymbolAddress((void**)&c1, g_col1);
  cudaGetSymbolAddress((void**)&cS, g_colS);
  cudaGetSymbolAddress((void**)&eT, g_embT);
  cudaGetSymbolAddress((void**)&se, g_se);
  cudaGetSymbolAddress((void**)&sq, g_sqn);
  cudaGetSymbolAddress((void**)&gi, g_idx);

  // 0: im2col conv_in
  im2col0_k<<<2048,256>>>(x, cS);
  // 1: conv_in GEMM: [128][48] x [48][524288] -> padded b1, bias+relu
  { dim3 g(4096,1,1); gemm_k<128,524288,48,1,2,256,256><<<g,256>>>(w_in, cS, b_in, b1); }
  // 2: im2col h1
  im2col1_k<<<512,256>>>(b1, c1);
  // 3 (PROFILED): h1 GEMM: [256][6272] x [6272][32768] -> padded b2, bias+relu
  { dim3 g(256,2,1); gemm_k<256,32768,6272,1,2,64,64><<<g,256>>>(w_h1, c1, b_h1, b2); }
  // 4: im2col h2
  im2col2_k<<<128,256>>>(b2, cS);
  // 5: h2 GEMM split-8 -> partials; epilogue -> b3 (unpadded [8,256,16,16])
  { dim3 g(16,2,8); gemm_k<256,2048,12544,8,1,0,0><<<g,256>>>(w_h2, cS, nullptr, pp); }
  epilogue_k<<<(256*2048+255)/256,256>>>(pp, b_h2, nullptr, b3, 256, 2048, 256, 8, 1, 16, 0);
  // h3: gather conv, split-16
  launch_old<256,16,16, 256,8,8, 3,3, 2,2, 1,1, 16,false>(w_h3, b3, nullptr, pp);
  epilogue_k<<<(256*512+255)/256,256>>>(pp, b_h3, nullptr, b4, 256, 512, 64, 16, 1, 8, 0);

  // residual block 0 (b4 >= 0, relu(h)==h)
  launch_old<256,8,8, 1024,8,8, 1,3, 1,1, 0,1, 8,false>(r0_w1, b4, nullptr, pp);
  epilogue_k<<<(1024*512+255)/256,256>>>(pp, nullptr, nullptr, tr, 1024, 512, 64, 8, 1, 8, 0);
  launch_old<1024,8,8, 256,8,8, 1,1, 1,1, 0,0, 8,false>(r0_w2, tr, nullptr, pp);
  epilogue_k<<<(256*512+255)/256,256>>>(pp, nullptr, b4, b5, 256, 512, 64, 8, 0, 8, 0);

  // residual block 1 (b5 may be negative -> relu on gather)
  launch_old<256,8,8, 1024,8,8, 1,3, 1,1, 0,1, 8,true>(r1_w1, b5, nullptr, pp);
  epilogue_k<<<(1024*512+255)/256,256>>>(pp, nullptr, nullptr, tr, 1024, 512, 64, 8, 1, 8, 0);
  launch_old<1024,8,8, 256,8,8, 1,1, 1,1, 0,0, 8,false>(r1_w2, tr, nullptr, pp);
  epilogue_k<<<(256*512+255)/256,256>>>(pp, nullptr, b5, b6, 256, 512, 64, 8, 1, 8, 0);

  // VQ
  transpose_emb_k<<<512,256>>>(emb, eT);
  emb_normsT_k<<<2,256>>>(eT, se);
  vq_rows_k<<<512,256>>>(b6, eT, emb, se, gi, sq);
  write_quant_k<<<512,256>>>(gi, emb, out);
  finalize_k<<<1,512>>>(gi, sq, out + 131072);
}

// round 13
// speedup vs baseline: 1.8327x; 1.2515x over previous
#include <cuda_runtime.h>
#include <cuda_bf16.h>
#include <cstdint>
#define DI __device__ __forceinline__

DI void ffma2(unsigned long long& c, unsigned long long a, unsigned long long b){
  asm("fma.rn.f32x2 %0, %1, %2, %0;" : "+l"(c) : "l"(a), "l"(b));
}
DI float2 funpack(unsigned long long v){ float2 f;
  asm("mov.b64 {%0, %1}, %2;" : "=f"(f.x), "=f"(f.y) : "l"(v)); return f; }
DI unsigned long long fdup(float a){ unsigned long long r;
  asm("mov.b64 %0, {%1, %1};" : "=l"(r) : "f"(a)); return r; }

__device__ float g_buf1[69222400];   // conv_in PADDED [8,128,260,260]
__device__ float g_buf2[9469952];    // h1 PADDED [8,256,68,68]
__device__ float g_buf3[524288];
__device__ float g_buf4[131072];
__device__ float g_tres[524288];
__device__ float g_buf5[131072];
__device__ float g_buf6[131072];
__device__ float g_part[4194304];
__device__ float g_colS[25690112];
__device__ __nv_bfloat16 g_Bh[268435456]; // [32768][8192]
__device__ __nv_bfloat16 g_Bl[268435456];
__device__ __nv_bfloat16 g_Ah[2097152];   // [256][8192]
__device__ __nv_bfloat16 g_Al[2097152];
__device__ float g_embT[131072];
__device__ float g_se[512];
__device__ int   g_idx[512];
__device__ float g_sqn[512];

// ============ FFMA2 GEMM on materialized im2col (proven) ============
template<int Mt,int Nt,int Kt,int NSPLIT,int MODE,int OHt,int OWt>
__global__ void __launch_bounds__(256,2)
gemm_k(const float* __restrict__ A, const float* __restrict__ B,
       const float* __restrict__ bias, float* __restrict__ out)
{
  constexpr int BK=8, Ksp=Kt/NSPLIT, NT=Ksp/BK, OHW=OHt*OWt;
  __shared__ float As[2][BK][128];
  __shared__ float Bs[2][BK][128];
  const int tid=threadIdx.x;
  const int n0=blockIdx.x*128, m0=blockIdx.y*128, kb=blockIdx.z*Ksp;
  const int am=tid>>1, ak=(tid&1)*4;
  const float* Aptr = A + (long)(m0+am)*Kt + kb + ak;
  const int gk=tid>>5, gn=(tid&31)*4;
  const float* Bptr = B + (long)(kb+gk)*Nt + n0 + gn;
  const int tx4=(tid&15)*4, ty4=(tid>>4)*4;
  unsigned long long acc[8][4];
#pragma unroll
  for(int i=0;i<8;i++){
#pragma unroll
    for(int p=0;p<4;p++) acc[i][p]=0ull; }
  float4 areg=*(const float4*)Aptr;
  float4 breg=*(const float4*)Bptr;
  As[0][ak+0][am]=areg.x; As[0][ak+1][am]=areg.y;
  As[0][ak+2][am]=areg.z; As[0][ak+3][am]=areg.w;
  *(float4*)&Bs[0][gk][gn]=breg;
  __syncthreads();
#pragma unroll 1
  for(int t=0;t<NT;t++){
    const int cur=t&1, nxt=cur^1; const bool more=(t+1<NT);
    float4 aN, bN;
    if(more){ aN=*(const float4*)(Aptr+(t+1)*BK); bN=*(const float4*)(Bptr+(long)(t+1)*BK*Nt); }
#pragma unroll
    for(int k=0;k<BK;k++){
      float4 a0=*(const float4*)&As[cur][k][ty4];
      float4 a1=*(const float4*)&As[cur][k][ty4+64];
      ulonglong2 B0=*(const ulonglong2*)&Bs[cur][k][tx4];
      ulonglong2 B1=*(const ulonglong2*)&Bs[cur][k][tx4+64];
      float av[8]={a0.x,a0.y,a0.z,a0.w,a1.x,a1.y,a1.z,a1.w};
#pragma unroll
      for(int i=0;i<8;i++){
        unsigned long long ad=fdup(av[i]);
        ffma2(acc[i][0],ad,B0.x); ffma2(acc[i][1],ad,B0.y);
        ffma2(acc[i][2],ad,B1.x); ffma2(acc[i][3],ad,B1.y);
      }
    }
    if(more){
      As[nxt][ak+0][am]=aN.x; As[nxt][ak+1][am]=aN.y;
      As[nxt][ak+2][am]=aN.z; As[nxt][ak+3][am]=aN.w;
      *(float4*)&Bs[nxt][gk][gn]=bN;
    }
    __syncthreads();
  }
  if(MODE==2){
    const int b=n0/OHW; const int pn0=n0-b*OHW;
#pragma unroll
    for(int i=0;i<8;i++){
      int m=m0+ty4+((i<4)?i:(60+i));
      float bv=bias[m];
      const int cols[4]={tx4,tx4+2,tx4+64,tx4+66};
#pragma unroll
      for(int p=0;p<4;p++){
        int nl=pn0+cols[p]; int oy=nl/OWt, ox=nl-oy*OWt;
        float2 w=funpack(acc[i][p]);
        w.x=fmaxf(w.x+bv,0.f); w.y=fmaxf(w.y+bv,0.f);
        *(float2*)(out + ((long)((b*Mt+m)*(OHt+4)+(oy+2)))*(OWt+4) + ox+2) = w;
      }
    }
  } else {
#pragma unroll
    for(int i=0;i<8;i++){
      int m=m0+ty4+((i<4)?i:(60+i));
      float* pp = out + ((long)blockIdx.z*Mt + m)*Nt + n0;
      float2 v0=funpack(acc[i][0]), v1=funpack(acc[i][1]);
      float2 v2=funpack(acc[i][2]), v3=funpack(acc[i][3]);
      *(float4*)(pp+tx4)    = make_float4(v0.x,v0.y,v1.x,v1.y);
      *(float4*)(pp+tx4+64) = make_float4(v2.x,v2.y,v3.x,v3.y);
    }
  }
}

// ---------------- im2col ----------------
__global__ void im2col0_k(const float* __restrict__ x, float* __restrict__ col){
  __shared__ float rows[4][520];
  const int tid=threadIdx.x, blk=blockIdx.x;
  const int b=blk>>8, oy=blk&255;
  for(int ic=0; ic<3; ic++){
    __syncthreads();
    for(int i=tid;i<4*520;i+=256) ((float*)rows)[i]=0.f;
    __syncthreads();
    for(int i=tid;i<4*128;i+=256){
      int ky=i>>7, c=(i&127)*4; int iy=2*oy-1+ky;
      if((unsigned)iy<512u)
        *(float4*)&rows[ky][4+c] = *(const float4*)(x + (((long)b*3+ic)*512+iy)*512 + c);
    }
    __syncthreads();
    for(int i=tid;i<16*64;i+=256){
      int kk=i>>6, q=i&63, ky=kk>>2, kx=kk&3, s=8*q+kx+3;
      float4 v=make_float4(rows[ky][s],rows[ky][s+2],rows[ky][s+4],rows[ky][s+6]);
      *(float4*)&col[(long)(ic*16+kk)*524288 + b*65536 + oy*256 + 4*q] = v;
    }
  }
}

DI uint32_t pk2(unsigned short a, unsigned short b){ return (uint32_t)a|((uint32_t)b<<16); }
DI void spl(float v, unsigned short& h, unsigned short& l){
  __nv_bfloat16 hb=__float2bfloat16(v);
  float r=v-__bfloat162float(hb);
  __nv_bfloat16 lb=__float2bfloat16(r);
  h=__bfloat16_as_ushort(hb); l=__bfloat16_as_ushort(lb);
}
// blocks 0..511: B = im2colT bf16 hi/lo [32768][8192]; 512..519: A split
__global__ void im2col1T_k(const float* __restrict__ b1, const float* __restrict__ w,
                           __nv_bfloat16* __restrict__ Bh, __nv_bfloat16* __restrict__ Bl,
                           __nv_bfloat16* __restrict__ Ah, __nv_bfloat16* __restrict__ Al){
  const int blk=blockIdx.x, tid=threadIdx.x;
  if(blk>=512){
    int base=(blk-512)*262144;
    for(int e=base+tid*8; e<base+262144; e+=2048){
      int m=e>>13, k0=e&8191;
      uint32_t uh[4], ul[4];
#pragma unroll
      for(int jj=0;jj<4;jj++){
        unsigned short hs[2], ls[2];
#pragma unroll
        for(int b2=0;b2<2;b2++){
          int k=k0+jj*2+b2, ic=k>>6, kk=k&63;
          spl((kk<49)? w[m*6272+ic*49+kk] : 0.f, hs[b2], ls[b2]);
        }
        uh[jj]=pk2(hs[0],hs[1]); ul[jj]=pk2(ls[0],ls[1]);
      }
      *(uint4*)(Ah+e)=make_uint4(uh[0],uh[1],uh[2],uh[3]);
      *(uint4*)(Al+e)=make_uint4(ul[0],ul[1],ul[2],ul[3]);
    }
    return;
  }
  __shared__ float rows[7][260];
  const int b=blk>>6, oy=blk&63;
  const int ox=tid&63, q=tid>>6;
  const long nrow=(long)(b*4096 + oy*64 + ox)*8192;
  for(int ic=0; ic<128; ic++){
    __syncthreads();
    const float* src = b1 + (((long)b*128+ic)*260 + 4*oy)*260;
    for(int i=tid;i<7*65;i+=256){
      int r=i/65, c=(i-r*65)*4;
      *(float4*)&rows[r][c] = *(const float4*)(src + r*260 + c);
    }
    __syncthreads();
    uint32_t uh[8], ul[8];
#pragma unroll
    for(int jj=0;jj<8;jj++){
      unsigned short hs[2], ls[2];
#pragma unroll
      for(int b2=0;b2<2;b2++){
        int kk=q*16+jj*2+b2; float v=0.f;
        if(kk<49){ int ky=kk/7, kx=kk-ky*7; v=rows[ky][4*ox+kx]; }
        spl(v, hs[b2], ls[b2]);
      }
      uh[jj]=pk2(hs[0],hs[1]); ul[jj]=pk2(ls[0],ls[1]);
    }
    long off=nrow + ic*64 + q*16;
    *(uint4*)(Bh+off)  =make_uint4(uh[0],uh[1],uh[2],uh[3]);
    *(uint4*)(Bh+off+8)=make_uint4(uh[4],uh[5],uh[6],uh[7]);
    *(uint4*)(Bl+off)  =make_uint4(ul[0],ul[1],ul[2],ul[3]);
    *(uint4*)(Bl+off+8)=make_uint4(ul[4],ul[5],ul[6],ul[7]);
  }
}

__global__ void im2col2_k(const float* __restrict__ b2, float* __restrict__ col){
  __shared__ float rows[7][68];
  const int tid=threadIdx.x, blk=blockIdx.x;
  const int b=blk>>4, oy=blk&15;
  for(int ic=0; ic<256; ic++){
    __syncthreads();
    const float* src = b2 + (((long)b*256+ic)*68 + 4*oy)*68;
    for(int i=tid;i<7*17;i+=256){
      int r=i/17, c=(i-r*17)*4;
      *(float4*)&rows[r][c] = *(const float4*)(src + r*68 + c);
    }
    __syncthreads();
    for(int i=tid;i<49*4;i+=256){
      int kk=i>>2, q=i&3, ky=kk/7, kx=kk-ky*7, s=16*q+kx;
      float4 v=make_float4(rows[ky][s],rows[ky][s+4],rows[ky][s+8],rows[ky][s+12]);
      *(float4*)&col[(long)(ic*49+kk)*2048 + b*256 + oy*16 + 4*q] = v;
    }
  }
}

// ================= h1 via mma.sync bf16 (HMMA, base-target-safe) =================
DI void ldm4(uint32_t* r, uint32_t addr){
  asm volatile("ldmatrix.sync.aligned.m8n8.x4.shared.b16 {%0,%1,%2,%3}, [%4];"
    :"=r"(r[0]),"=r"(r[1]),"=r"(r[2]),"=r"(r[3]):"r"(addr));
}
DI void mma16816(float* c, const uint32_t* a, uint32_t b0, uint32_t b1){
  asm volatile("mma.sync.aligned.m16n8k16.row.col.f32.bf16.bf16.f32 "
    "{%0,%1,%2,%3},{%4,%5,%6,%7},{%8,%9},{%0,%1,%2,%3};"
    :"+f"(c[0]),"+f"(c[1]),"+f"(c[2]),"+f"(c[3])
    :"r"(a[0]),"r"(a[1]),"r"(a[2]),"r"(a[3]),"r"(b0),"r"(b1));
}

// CTA 128x128, BK=32, 8 warps (4m x 2n), warp tile 32x64. 3-pass hi/lo.
__global__ void __launch_bounds__(256,1)
h1_mma_k(const __nv_bfloat16* __restrict__ Ah, const __nv_bfloat16* __restrict__ Al,
         const __nv_bfloat16* __restrict__ Bh, const __nv_bfloat16* __restrict__ Bl,
         const float* __restrict__ bias, float* __restrict__ out)
{
  extern __shared__ __nv_bfloat16 sm[];        // [2buf][2split][128][40] A then B
  __nv_bfloat16* smA = sm;                     // 20480 elems
  __nv_bfloat16* smB = sm + 20480;
  const int tid=threadIdx.x, lane=tid&31, wid=tid>>5;
  const int wm=wid>>1, wn=wid&1;
  const int n0=blockIdx.x*128, m0=blockIdx.y*128;
  const int r=tid>>1, jj=(tid&1)*16;

  float acc[2][8][4];
#pragma unroll
  for(int i=0;i<2;i++)
#pragma unroll
    for(int j=0;j<8;j++)
#pragma unroll
      for(int p=0;p<4;p++) acc[i][j][p]=0.f;

  uint4 pA0,pA1,pA2,pA3,pB0,pB1,pB2,pB3;
  const long abase=(long)(m0+r)*8192+jj, bbase=(long)(n0+r)*8192+jj;
#define GLOAD(t) { long ao=abase+(t)*32, bo=bbase+(t)*32; \
  pA0=*(const uint4*)(Ah+ao); pA1=*(const uint4*)(Ah+ao+8); \
  pA2=*(const uint4*)(Al+ao); pA3=*(const uint4*)(Al+ao+8); \
  pB0=*(const uint4*)(Bh+bo); pB1=*(const uint4*)(Bh+bo+8); \
  pB2=*(const uint4*)(Bl+bo); pB3=*(const uint4*)(Bl+bo+8); }
#define SSTORE(buf) { __nv_bfloat16* p=smA+(((buf)*2)*128+r)*40+jj; \
  *(uint4*)p=pA0; *(uint4*)(p+8)=pA1; \
  *(uint4*)(p+5120)=pA2; *(uint4*)(p+5128)=pA3; \
  p=smB+(((buf)*2)*128+r)*40+jj; \
  *(uint4*)p=pB0; *(uint4*)(p+8)=pB1; \
  *(uint4*)(p+5120)=pB2; *(uint4*)(p+5128)=pB3; }

  GLOAD(0); SSTORE(0);
  __syncthreads();

#pragma unroll 1
  for(int t=0;t<256;t++){
    const int buf=t&1;
    if(t+1<256) GLOAD(t+1);
#pragma unroll
    for(int ks=0;ks<2;ks++){
      const int ksub=ks*16;
      uint32_t af[2][2][4];
#pragma unroll
      for(int mt=0;mt<2;mt++)
#pragma unroll
        for(int s=0;s<2;s++){
          int row=wm*32+mt*16+(lane&15);
          int ce=ksub+(lane>>4)*8;
          ldm4(af[mt][s], (uint32_t)__cvta_generic_to_shared(smA+((buf*2+s)*128+row)*40+ce));
        }
      uint32_t bfm[4][2][4];
#pragma unroll
      for(int p2=0;p2<4;p2++)
#pragma unroll
        for(int s=0;s<2;s++){
          int g=lane>>3, i=lane&7;
          int row=wn*64+p2*16+((g>>1)<<3)+i;
          int ce=ksub+((g&1)<<3);
          ldm4(bfm[p2][s], (uint32_t)__cvta_generic_to_shared(smB+((buf*2+s)*128+row)*40+ce));
        }
#pragma unroll
      for(int mt=0;mt<2;mt++)
#pragma unroll
        for(int nt=0;nt<8;nt++){
          uint32_t b0h=bfm[nt>>1][0][(nt&1)*2], b1h=bfm[nt>>1][0][(nt&1)*2+1];
          uint32_t b0l=bfm[nt>>1][1][(nt&1)*2], b1l=bfm[nt>>1][1][(nt&1)*2+1];
          mma16816(acc[mt][nt], af[mt][0], b0h, b1h);
          mma16816(acc[mt][nt], af[mt][0], b0l, b1l);
          mma16816(acc[mt][nt], af[mt][1], b0h, b1h);
        }
    }
    if(t+1<256) SSTORE(buf^1);
    __syncthreads();
  }

  // epilogue: bias + relu -> padded b2 [b][256][68][68] @ +2
  // c0,c1 -> row m; c2,c3 -> row m+8  (m-stride = 68*68 elements per channel row!)
#pragma unroll
  for(int mt=0;mt<2;mt++){
    int m=m0+wm*32+mt*16+(lane>>2);
    float bv0=bias[m], bv1=bias[m+8];
#pragma unroll
    for(int nt=0;nt<8;nt++){
      float* c=acc[mt][nt];
      int nI=n0+wn*64+nt*8+(lane&3)*2;
      int b=nI>>12, p=nI&4095, oy=p>>6, ox=p&63;
      long rb=((long)(b*256+m)*68+oy+2)*68+ox+2;
      float2 v0; v0.x=fmaxf(c[0]+bv0,0.f); v0.y=fmaxf(c[1]+bv0,0.f);
      float2 v1; v1.x=fmaxf(c[2]+bv1,0.f); v1.y=fmaxf(c[3]+bv1,0.f);
      *(float2*)(out+rb)=v0;
      *(float2*)(out+rb+8*68*68)=v1;   // FIX: advance m by 8 (was 8*68 = oy+8, wrong)
    }
  }
}

// ============ gather conv (residual layers + h3) ============
template<int IC,int IH,int IW,int OC,int OH,int OW,
         int KH,int KW,int SH,int SW,int PH,int PW,int NSPLIT,bool RELU_IN>
__global__ void __launch_bounds__(256,2)
conv_gemm(const float* __restrict__ W, const float* __restrict__ X,
          const float* __restrict__ bias, float* __restrict__ out)
{
  constexpr int BM=128, BN=128, BK=8;
  constexpr int Ktot=IC*KH*KW, Ksp=Ktot/NSPLIT, NT=Ksp/BK;
  constexpr int OHW=OH*OW, Ntot=8*OHW;
  __shared__ float As[2][BK][BM];
  __shared__ float Bs[2][BK][BN];
  const int tid=threadIdx.x;
  const int n0=blockIdx.x*BN, m0=blockIdx.y*BM, kb0=blockIdx.z*Ksp;
  const int am=tid>>1, ak=(tid&1)*4;
  const float* Aptr = W + (m0+am)*Ktot + kb0 + ak;
  const int gk=tid>>5, gn=(tid&31)*4;
  int nbase[4], iy0[4], ix0[4];
#pragma unroll
  for(int j=0;j<4;j++){
    int n=n0+gn+j; int b=n/OHW, p=n-b*OHW;
    int oy=p/OW, ox=p-oy*OW;
    iy0[j]=oy*SH-PH; ix0[j]=ox*SW-PW;
    nbase[j]=b*(IC*IH*IW);
  }
  const int tx4=(tid&15)*4, ty4=(tid>>4)*4;
  unsigned long long acc[8][4];
#pragma unroll
  for(int i=0;i<8;i++){
#pragma unroll
    for(int p=0;p<4;p++) acc[i][p]=0ull; }
  float4 areg=*(const float4*)Aptr;
  float br[4];
  {
    int kg=kb0+gk, ic=kg/(KH*KW), r=kg-ic*(KH*KW), ky=r/KW, kx=r-ky*KW;
#pragma unroll
    for(int j=0;j<4;j++){
      int iy=iy0[j]+ky, ix=ix0[j]+kx; float v=0.f;
      if((unsigned)iy<(unsigned)IH && (unsigned)ix<(unsigned)IW)
        v=X[nbase[j]+ic*(IH*IW)+iy*IW+ix];
      if(RELU_IN) v=fmaxf(v,0.f);
      br[j]=v;
    }
  }
  As[0][ak+0][am]=areg.x; As[0][ak+1][am]=areg.y;
  As[0][ak+2][am]=areg.z; As[0][ak+3][am]=areg.w;
  *(float4*)&Bs[0][gk][gn]=make_float4(br[0],br[1],br[2],br[3]);
  __syncthreads();
#pragma unroll 1
  for(int t=0;t<NT;t++){
    const int cur=t&1, nxt=cur^1; const bool more=(t+1<NT);
    float4 aN; float bN[4];
    if(more){
      aN=*(const float4*)(Aptr+(t+1)*BK);
      int kg=kb0+(t+1)*BK+gk, ic=kg/(KH*KW), r=kg-ic*(KH*KW), ky=r/KW, kx=r-ky*KW;
#pragma unroll
      for(int j=0;j<4;j++){
        int iy=iy0[j]+ky, ix=ix0[j]+kx; float v=0.f;
        if((unsigned)iy<(unsigned)IH && (unsigned)ix<(unsigned)IW)
          v=X[nbase[j]+ic*(IH*IW)+iy*IW+ix];
        if(RELU_IN) v=fmaxf(v,0.f);
        bN[j]=v;
      }
    }
#pragma unroll
    for(int k=0;k<BK;k++){
      float4 a0=*(const float4*)&As[cur][k][ty4];
      float4 a1=*(const float4*)&As[cur][k][ty4+64];
      ulonglong2 B0=*(const ulonglong2*)&Bs[cur][k][tx4];
      ulonglong2 B1=*(const ulonglong2*)&Bs[cur][k][tx4+64];
      float av[8]={a0.x,a0.y,a0.z,a0.w,a1.x,a1.y,a1.z,a1.w};
#pragma unroll
      for(int i=0;i<8;i++){
        unsigned long long ad=fdup(av[i]);
        ffma2(acc[i][0],ad,B0.x); ffma2(acc[i][1],ad,B0.y);
        ffma2(acc[i][2],ad,B1.x); ffma2(acc[i][3],ad,B1.y);
      }
    }
    if(more){
      As[nxt][ak+0][am]=aN.x; As[nxt][ak+1][am]=aN.y;
      As[nxt][ak+2][am]=aN.z; As[nxt][ak+3][am]=aN.w;
      *(float4*)&Bs[nxt][gk][gn]=make_float4(bN[0],bN[1],bN[2],bN[3]);
    }
    __syncthreads();
  }
#pragma unroll
  for(int i=0;i<8;i++){
    int m=m0+ty4+((i<4)?i:(60+i));
    float* pp = out + ((long)blockIdx.z*OC+m)*Ntot + n0;
    float2 v0=funpack(acc[i][0]), v1=funpack(acc[i][1]);
    float2 v2=funpack(acc[i][2]), v3=funpack(acc[i][3]);
    *(float4*)(pp+tx4)    = make_float4(v0.x,v0.y,v1.x,v1.y);
    *(float4*)(pp+tx4+64) = make_float4(v2.x,v2.y,v3.x,v3.y);
  }
}

__global__ void epilogue_k(const float* __restrict__ part, const float* __restrict__ bias,
                           const float* __restrict__ add, float* __restrict__ out,
                           int M, int N, int OHW, int nsplit, int relu, int OWd, int pad)
{
  int gid=blockIdx.x*256+threadIdx.x;
  if(gid>=M*N) return;
  int m=gid/N, n=gid-m*N;
  float s=0.f;
  for(int sp=0; sp<nsplit; sp++) s += part[((long)sp*M+m)*N+n];
  if(bias) s += bias[m];
  int b=n/OHW, p=n-b*OHW;
  if(add) s += add[((long)b*M+m)*OHW+p];
  if(relu) s=fmaxf(s,0.f);
  long oa;
  if(pad){
    int oy=p/OWd, ox=p-oy*OWd, OHd=OHW/OWd;
    oa=((long)((b*M+m)*(OHd+4)+(oy+2)))*(OWd+4)+ox+2;
  } else oa=((long)b*M+m)*OHW+p;
  out[oa]=s;
}

__global__ void transpose_emb_k(const float* __restrict__ emb, float* __restrict__ embT){
  int gid=blockIdx.x*256+threadIdx.x;
  embT[gid]=emb[(gid&511)*256+(gid>>9)];
}
__global__ void emb_normsT_k(const float* __restrict__ embT, float* __restrict__ se){
  int c=blockIdx.x*256+threadIdx.x; float s=0.f;
  for(int d=0; d<256; d++){ float v=embT[d*512+c]; s=fmaf(v,v,s); }
  se[c]=s;
}
__global__ void vq_rows_k(const float* __restrict__ lat, const float* __restrict__ embT,
                          const float* __restrict__ emb, const float* __restrict__ se,
                          int* __restrict__ idxo, float* __restrict__ sqo)
{
  __shared__ float sl[256]; __shared__ float sval[256]; __shared__ int sidx[256];
  int r=blockIdx.x, t=threadIdx.x, b=r>>6, p=r&63;
  sl[t]=lat[((b<<8)+t)*64+p];
  __syncthreads();
  float fn=0.f;
  for(int k=0;k<256;k++) fn=fmaf(sl[k],sl[k],fn);
  float d0=0.f,d1=0.f;
  for(int k=0;k<256;k++){
    float v=sl[k];
    d0=fmaf(embT[k*512+t],v,d0); d1=fmaf(embT[k*512+t+256],v,d1);
  }
  float dist0=fn+se[t]-2.f*d0, dist1=fn+se[t+256]-2.f*d1;
  float best; int bi;
  if(dist1<dist0){best=dist1; bi=t+256;} else {best=dist0; bi=t;}
  sval[t]=best; sidx[t]=bi;
  __syncthreads();
  for(int s=128;s>0;s>>=1){
    if(t<s){
      float v2=sval[t+s]; int i2=sidx[t+s];
      if(v2<sval[t] || (v2==sval[t] && i2<sidx[t])){ sval[t]=v2; sidx[t]=i2; }
    }
    __syncthreads();
  }
  int w=sidx[0];
  if(t==0) idxo[r]=w;
  __syncthreads();
  float diff=emb[w*256+t]-sl[t];
  sval[t]=diff*diff;
  __syncthreads();
  for(int s=128;s>0;s>>=1){
    if(t<s) sval[t]+=sval[t+s];
    __syncthreads();
  }
  if(t==0) sqo[r]=sval[0];
}
__global__ void write_quant_k(const int* __restrict__ idx, const float* __restrict__ emb,
                              float* __restrict__ out){
  int gid=blockIdx.x*256+threadIdx.x;
  out[gid]=emb[idx[((gid>>14)<<6)+(gid&63)]*256+((gid>>6)&255)];
}
__global__ void finalize_k(const int* __restrict__ idx, const float* __restrict__ sq,
                           float* __restrict__ out2){
  __shared__ float sh[512]; __shared__ float ss[512];
  int t=threadIdx.x; int cnt=0;
  for(int r=0;r<512;r++) cnt += (idx[r]==t)?1:0;
  float pr=(float)cnt*(1.f/512.f);
  sh[t]=-pr*logf(pr+1e-10f); ss[t]=sq[t];
  __syncthreads();
  for(int s=256;s>0;s>>=1){
    if(t<s){ sh[t]+=sh[t+s]; ss[t]+=ss[t+s]; }
    __syncthreads();
  }
  if(t==0){ out2[0]=2.f*ss[0]*(1.f/131072.f); out2[1]=expf(sh[0]); }
}

template<int IC,int IH,int IW,int OC,int OH,int OW,int KH,int KW,
         int SH,int SW,int PH,int PW,int NSPLIT,bool RIN>
static void launch_old(const float* W, const float* X, const float* bias, float* out){
  dim3 g((8*OH*OW)/128, OC/128, NSPLIT);
  conv_gemm<IC,IH,IW,OC,OH,OW,KH,KW,SH,SW,PH,PW,NSPLIT,RIN><<<g,256>>>(W,X,bias,out);
}

extern "C" void kernel_launch(void* const* d_in, const int* in_sizes, int n_in,
                              void* d_out, int out_size)
{
  const float* x     = (const float*)d_in[0];
  const float* w_in  = (const float*)d_in[1];
  const float* b_in  = (const float*)d_in[2];
  const float* w_h1  = (const float*)d_in[3];
  const float* b_h1  = (const float*)d_in[4];
  const float* w_h2  = (const float*)d_in[5];
  const float* b_h2  = (const float*)d_in[6];
  const float* w_h3  = (const float*)d_in[7];
  const float* b_h3  = (const float*)d_in[8];
  const float* r0_w1 = (const float*)d_in[9];
  const float* r0_w2 = (const float*)d_in[10];
  const float* r1_w1 = (const float*)d_in[11];
  const float* r1_w2 = (const float*)d_in[12];
  const float* emb   = (const float*)d_in[13];
  float* out = (float*)d_out;

  float *b1,*b2,*b3,*b4,*b5,*b6,*tr,*pp,*cS,*eT,*se,*sq; int* gi;
  __nv_bfloat16 *Ah,*Al,*Bh,*Bl;
  cudaGetSymbolAddress((void**)&b1,g_buf1);
  cudaGetSymbolAddress((void**)&b2,g_buf2);
  cudaGetSymbolAddress((void**)&b3,g_buf3);
  cudaGetSymbolAddress((void**)&b4,g_buf4);
  cudaGetSymbolAddress((void**)&b5,g_buf5);
  cudaGetSymbolAddress((void**)&b6,g_buf6);
  cudaGetSymbolAddress((void**)&tr,g_tres);
  cudaGetSymbolAddress((void**)&pp,g_part);
  cudaGetSymbolAddress((void**)&cS,g_colS);
  cudaGetSymbolAddress((void**)&eT,g_embT);
  cudaGetSymbolAddress((void**)&se,g_se);
  cudaGetSymbolAddress((void**)&sq,g_sqn);
  cudaGetSymbolAddress((void**)&gi,g_idx);
  cudaGetSymbolAddress((void**)&Ah,g_Ah);
  cudaGetSymbolAddress((void**)&Al,g_Al);
  cudaGetSymbolAddress((void**)&Bh,g_Bh);
  cudaGetSymbolAddress((void**)&Bl,g_Bl);

  cudaFuncSetAttribute(h1_mma_k, cudaFuncAttributeMaxDynamicSharedMemorySize, 81920);

  im2col0_k<<<2048,256>>>(x, cS);                                             // 0
  { dim3 g(4096,1,1); gemm_k<128,524288,48,1,2,256,256><<<g,256>>>(w_in, cS, b_in, b1); } // 1
  im2col1T_k<<<520,256>>>(b1, w_h1, Bh, Bl, Ah, Al);                          // 2
  h1_mma_k<<<dim3(256,2),256,81920>>>(Ah, Al, Bh, Bl, b_h1, b2);              // 3 PROFILED
  im2col2_k<<<128,256>>>(b2, cS);
  { dim3 g(16,2,8); gemm_k<256,2048,12544,8,1,0,0><<<g,256>>>(w_h2, cS, nullptr, pp); }
  epilogue_k<<<(256*2048+255)/256,256>>>(pp, b_h2, nullptr, b3, 256, 2048, 256, 8, 1, 16, 0);
  launch_old<256,16,16, 256,8,8, 3,3, 2,2, 1,1, 16,false>(w_h3, b3, nullptr, pp);
  epilogue_k<<<(256*512+255)/256,256>>>(pp, b_h3, nullptr, b4, 256, 512, 64, 16, 1, 8, 0);

  launch_old<256,8,8, 1024,8,8, 1,3, 1,1, 0,1, 8,false>(r0_w1, b4, nullptr, pp);
  epilogue_k<<<(1024*512+255)/256,256>>>(pp, nullptr, nullptr, tr, 1024, 512, 64, 8, 1, 8, 0);
  launch_old<1024,8,8, 256,8,8, 1,1, 1,1, 0,0, 8,false>(r0_w2, tr, nullptr, pp);
  epilogue_k<<<(256*512+255)/256,256>>>(pp, nullptr, b4, b5, 256, 512, 64, 8, 0, 8, 0);

  launch_old<256,8,8, 1024,8,8, 1,3, 1,1, 0,1, 8,true>(r1_w1, b5, nullptr, pp);
  epilogue_k<<<(1024*512+255)/256,256>>>(pp, nullptr, nullptr, tr, 1024, 512, 64, 8, 1, 8, 0);
  launch_old<1024,8,8, 256,8,8, 1,1, 1,1, 0,0, 8,false>(r1_w2, tr, nullptr, pp);
  epilogue_k<<<(256*512+255)/256,256>>>(pp, nullptr, b5, b6, 256, 512, 64, 8, 1, 8, 0);

  transpose_emb_k<<<512,256>>>(emb, eT);
  emb_normsT_k<<<2,256>>>(eT, se);
  vq_rows_k<<<512,256>>>(b6, eT, emb, se, gi, sq);
  write_quant_k<<<512,256>>>(gi, emb, out);
  finalize_k<<<1,512>>>(gi, sq, out + 131072);
}

// round 17
// speedup vs baseline: 1.8361x; 1.0019x over previous
#include <cuda_runtime.h>
#include <cuda_bf16.h>
#include <cstdint>
#define DI __device__ __forceinline__

DI void ffma2(unsigned long long& c, unsigned long long a, unsigned long long b){
  asm("fma.rn.f32x2 %0, %1, %2, %0;" : "+l"(c) : "l"(a), "l"(b));
}
DI float2 funpack(unsigned long long v){ float2 f;
  asm("mov.b64 {%0, %1}, %2;" : "=f"(f.x), "=f"(f.y) : "l"(v)); return f; }
DI unsigned long long fdup(float a){ unsigned long long r;
  asm("mov.b64 %0, {%1, %1};" : "=l"(r) : "f"(a)); return r; }
DI void cpa16(uint32_t dst, const void* src){
  asm volatile("cp.async.ca.shared.global [%0], [%1], 16;"::"r"(dst),"l"(src):"memory");
}
DI void cpacommit(){ asm volatile("cp.async.commit_group;":::"memory"); }
DI void cpawait2(){ asm volatile("cp.async.wait_group 2;":::"memory"); }

__device__ float g_buf1[69222400];   // conv_in PADDED [8,128,260,260]
__device__ float g_buf2[9469952];    // h1 PADDED [8,256,68,68]
__device__ float g_buf3[524288];
__device__ float g_buf4[131072];
__device__ float g_tres[524288];
__device__ float g_buf5[131072];
__device__ float g_buf6[131072];
__device__ float g_part[4194304];
__device__ float g_colS[25690112];
__device__ __nv_bfloat16 g_Bh[268435456]; // [32768][8192]
__device__ __nv_bfloat16 g_Bl[268435456];
__device__ __nv_bfloat16 g_Ah[2097152];   // [256][8192]
__device__ __nv_bfloat16 g_Al[2097152];
__device__ float g_embT[131072];
__device__ float g_se[512];
__device__ int   g_idx[512];
__device__ float g_sqn[512];

// ============ FFMA2 GEMM on materialized im2col (proven) ============
template<int Mt,int Nt,int Kt,int NSPLIT,int MODE,int OHt,int OWt>
__global__ void __launch_bounds__(256,2)
gemm_k(const float* __restrict__ A, const float* __restrict__ B,
       const float* __restrict__ bias, float* __restrict__ out)
{
  constexpr int BK=8, Ksp=Kt/NSPLIT, NT=Ksp/BK, OHW=OHt*OWt;
  __shared__ float As[2][BK][128];
  __shared__ float Bs[2][BK][128];
  const int tid=threadIdx.x;
  const int n0=blockIdx.x*128, m0=blockIdx.y*128, kb=blockIdx.z*Ksp;
  const int am=tid>>1, ak=(tid&1)*4;
  const float* Aptr = A + (long)(m0+am)*Kt + kb + ak;
  const int gk=tid>>5, gn=(tid&31)*4;
  const float* Bptr = B + (long)(kb+gk)*Nt + n0 + gn;
  const int tx4=(tid&15)*4, ty4=(tid>>4)*4;
  unsigned long long acc[8][4];
#pragma unroll
  for(int i=0;i<8;i++){
#pragma unroll
    for(int p=0;p<4;p++) acc[i][p]=0ull; }
  float4 areg=*(const float4*)Aptr;
  float4 breg=*(const float4*)Bptr;
  As[0][ak+0][am]=areg.x; As[0][ak+1][am]=areg.y;
  As[0][ak+2][am]=areg.z; As[0][ak+3][am]=areg.w;
  *(float4*)&Bs[0][gk][gn]=breg;
  __syncthreads();
#pragma unroll 1
  for(int t=0;t<NT;t++){
    const int cur=t&1, nxt=cur^1; const bool more=(t+1<NT);
    float4 aN, bN;
    if(more){ aN=*(const float4*)(Aptr+(t+1)*BK); bN=*(const float4*)(Bptr+(long)(t+1)*BK*Nt); }
#pragma unroll
    for(int k=0;k<BK;k++){
      float4 a0=*(const float4*)&As[cur][k][ty4];
      float4 a1=*(const float4*)&As[cur][k][ty4+64];
      ulonglong2 B0=*(const ulonglong2*)&Bs[cur][k][tx4];
      ulonglong2 B1=*(const ulonglong2*)&Bs[cur][k][tx4+64];
      float av[8]={a0.x,a0.y,a0.z,a0.w,a1.x,a1.y,a1.z,a1.w};
#pragma unroll
      for(int i=0;i<8;i++){
        unsigned long long ad=fdup(av[i]);
        ffma2(acc[i][0],ad,B0.x); ffma2(acc[i][1],ad,B0.y);
        ffma2(acc[i][2],ad,B1.x); ffma2(acc[i][3],ad,B1.y);
      }
    }
    if(more){
      As[nxt][ak+0][am]=aN.x; As[nxt][ak+1][am]=aN.y;
      As[nxt][ak+2][am]=aN.z; As[nxt][ak+3][am]=aN.w;
      *(float4*)&Bs[nxt][gk][gn]=bN;
    }
    __syncthreads();
  }
  if(MODE==2){
    const int b=n0/OHW; const int pn0=n0-b*OHW;
#pragma unroll
    for(int i=0;i<8;i++){
      int m=m0+ty4+((i<4)?i:(60+i));
      float bv=bias[m];
      const int cols[4]={tx4,tx4+2,tx4+64,tx4+66};
#pragma unroll
      for(int p=0;p<4;p++){
        int nl=pn0+cols[p]; int oy=nl/OWt, ox=nl-oy*OWt;
        float2 w=funpack(acc[i][p]);
        w.x=fmaxf(w.x+bv,0.f); w.y=fmaxf(w.y+bv,0.f);
        *(float2*)(out + ((long)((b*Mt+m)*(OHt+4)+(oy+2)))*(OWt+4) + ox+2) = w;
      }
    }
  } else {
#pragma unroll
    for(int i=0;i<8;i++){
      int m=m0+ty4+((i<4)?i:(60+i));
      float* pp = out + ((long)blockIdx.z*Mt + m)*Nt + n0;
      float2 v0=funpack(acc[i][0]), v1=funpack(acc[i][1]);
      float2 v2=funpack(acc[i][2]), v3=funpack(acc[i][3]);
      *(float4*)(pp+tx4)    = make_float4(v0.x,v0.y,v1.x,v1.y);
      *(float4*)(pp+tx4+64) = make_float4(v2.x,v2.y,v3.x,v3.y);
    }
  }
}

// ---------------- im2col ----------------
__global__ void im2col0_k(const float* __restrict__ x, float* __restrict__ col){
  __shared__ float rows[4][520];
  const int tid=threadIdx.x, blk=blockIdx.x;
  const int b=blk>>8, oy=blk&255;
  for(int ic=0; ic<3; ic++){
    __syncthreads();
    for(int i=tid;i<4*520;i+=256) ((float*)rows)[i]=0.f;
    __syncthreads();
    for(int i=tid;i<4*128;i+=256){
      int ky=i>>7, c=(i&127)*4; int iy=2*oy-1+ky;
      if((unsigned)iy<512u)
        *(float4*)&rows[ky][4+c] = *(const float4*)(x + (((long)b*3+ic)*512+iy)*512 + c);
    }
    __syncthreads();
    for(int i=tid;i<16*64;i+=256){
      int kk=i>>6, q=i&63, ky=kk>>2, kx=kk&3, s=8*q+kx+3;
      float4 v=make_float4(rows[ky][s],rows[ky][s+2],rows[ky][s+4],rows[ky][s+6]);
      *(float4*)&col[(long)(ic*16+kk)*524288 + b*65536 + oy*256 + 4*q] = v;
    }
  }
}

DI uint32_t pk2(unsigned short a, unsigned short b){ return (uint32_t)a|((uint32_t)b<<16); }
DI void spl(float v, unsigned short& h, unsigned short& l){
  __nv_bfloat16 hb=__float2bfloat16(v);
  float r=v-__bfloat162float(hb);
  __nv_bfloat16 lb=__float2bfloat16(r);
  h=__bfloat16_as_ushort(hb); l=__bfloat16_as_ushort(lb);
}
// blocks 0..511: B = im2colT bf16 hi/lo [32768][8192]; 512..519: A split
__global__ void im2col1T_k(const float* __restrict__ b1, const float* __restrict__ w,
                           __nv_bfloat16* __restrict__ Bh, __nv_bfloat16* __restrict__ Bl,
                           __nv_bfloat16* __restrict__ Ah, __nv_bfloat16* __restrict__ Al){
  const int blk=blockIdx.x, tid=threadIdx.x;
  if(blk>=512){
    int base=(blk-512)*262144;
    for(int e=base+tid*8; e<base+262144; e+=2048){
      int m=e>>13, k0=e&8191;
      uint32_t uh[4], ul[4];
#pragma unroll
      for(int jj=0;jj<4;jj++){
        unsigned short hs[2], ls[2];
#pragma unroll
        for(int b2=0;b2<2;b2++){
          int k=k0+jj*2+b2, ic=k>>6, kk=k&63;
          spl((kk<49)? w[m*6272+ic*49+kk] : 0.f, hs[b2], ls[b2]);
        }
        uh[jj]=pk2(hs[0],hs[1]); ul[jj]=pk2(ls[0],ls[1]);
      }
      *(uint4*)(Ah+e)=make_uint4(uh[0],uh[1],uh[2],uh[3]);
      *(uint4*)(Al+e)=make_uint4(ul[0],ul[1],ul[2],ul[3]);
    }
    return;
  }
  __shared__ float rows[7][260];
  const int b=blk>>6, oy=blk&63;
  const int ox=tid&63, q=tid>>6;
  const long nrow=(long)(b*4096 + oy*64 + ox)*8192;
  for(int ic=0; ic<128; ic++){
    __syncthreads();
    const float* src = b1 + (((long)b*128+ic)*260 + 4*oy)*260;
    for(int i=tid;i<7*65;i+=256){
      int r=i/65, c=(i-r*65)*4;
      *(float4*)&rows[r][c] = *(const float4*)(src + r*260 + c);
    }
    __syncthreads();
    uint32_t uh[8], ul[8];
#pragma unroll
    for(int jj=0;jj<8;jj++){
      unsigned short hs[2], ls[2];
#pragma unroll
      for(int b2=0;b2<2;b2++){
        int kk=q*16+jj*2+b2; float v=0.f;
        if(kk<49){ int ky=kk/7, kx=kk-ky*7; v=rows[ky][4*ox+kx]; }
        spl(v, hs[b2], ls[b2]);
      }
      uh[jj]=pk2(hs[0],hs[1]); ul[jj]=pk2(ls[0],ls[1]);
    }
    long off=nrow + ic*64 + q*16;
    *(uint4*)(Bh+off)  =make_uint4(uh[0],uh[1],uh[2],uh[3]);
    *(uint4*)(Bh+off+8)=make_uint4(uh[4],uh[5],uh[6],uh[7]);
    *(uint4*)(Bl+off)  =make_uint4(ul[0],ul[1],ul[2],ul[3]);
    *(uint4*)(Bl+off+8)=make_uint4(ul[4],ul[5],ul[6],ul[7]);
  }
}

__global__ void im2col2_k(const float* __restrict__ b2, float* __restrict__ col){
  __shared__ float rows[7][68];
  const int tid=threadIdx.x, blk=blockIdx.x;
  const int b=blk>>4, oy=blk&15;
  for(int ic=0; ic<256; ic++){
    __syncthreads();
    const float* src = b2 + (((long)b*256+ic)*68 + 4*oy)*68;
    for(int i=tid;i<7*17;i+=256){
      int r=i/17, c=(i-r*17)*4;
      *(float4*)&rows[r][c] = *(const float4*)(src + r*68 + c);
    }
    __syncthreads();
    for(int i=tid;i<49*4;i+=256){
      int kk=i>>2, q=i&3, ky=kk/7, kx=kk-ky*7, s=16*q+kx;
      float4 v=make_float4(rows[ky][s],rows[ky][s+4],rows[ky][s+8],rows[ky][s+12]);
      *(float4*)&col[(long)(ic*49+kk)*2048 + b*256 + oy*16 + 4*q] = v;
    }
  }
}

// ================= h1 via mma.sync bf16, 4-stage cp.async pipeline =================
DI void ldm4(uint32_t* r, uint32_t addr){
  asm volatile("ldmatrix.sync.aligned.m8n8.x4.shared.b16 {%0,%1,%2,%3}, [%4];"
    :"=r"(r[0]),"=r"(r[1]),"=r"(r[2]),"=r"(r[3]):"r"(addr));
}
DI void mma16816(float* c, const uint32_t* a, uint32_t b0, uint32_t b1){
  asm volatile("mma.sync.aligned.m16n8k16.row.col.f32.bf16.bf16.f32 "
    "{%0,%1,%2,%3},{%4,%5,%6,%7},{%8,%9},{%0,%1,%2,%3};"
    :"+f"(c[0]),"+f"(c[1]),"+f"(c[2]),"+f"(c[3])
    :"r"(a[0]),"r"(a[1]),"r"(a[2]),"r"(a[3]),"r"(b0),"r"(b1));
}

// CTA 128x128, BK=32, 8 warps (4m x 2n), warp tile 32x64, 3-pass hi/lo.
// smem: A [4st][2split][128][40] then B same; 163840 bytes total.
__global__ void __launch_bounds__(256,1)
h1_mma_k(const __nv_bfloat16* __restrict__ Ah, const __nv_bfloat16* __restrict__ Al,
         const __nv_bfloat16* __restrict__ Bh, const __nv_bfloat16* __restrict__ Bl,
         const float* __restrict__ bias, float* __restrict__ out)
{
  extern __shared__ __nv_bfloat16 sm[];
  const int tid=threadIdx.x, lane=tid&31, wid=tid>>5;
  const int wm=wid>>1, wn=wid&1;
  const int n0=blockIdx.x*128, m0=blockIdx.y*128;
  const int r=tid>>1, jj=(tid&1)*16;
  const uint32_t smA0=(uint32_t)__cvta_generic_to_shared(sm);
  const uint32_t smB0=smA0+81920;               // 4*2*128*40*2 bytes
  const uint32_t offT=(uint32_t)(r*40+jj)*2;
  const long abase=(long)(m0+r)*8192+jj, bbase=(long)(n0+r)*8192+jj;

  float acc[2][8][4];
#pragma unroll
  for(int i=0;i<2;i++)
#pragma unroll
    for(int j=0;j<8;j++)
#pragma unroll
      for(int p=0;p<4;p++) acc[i][j][p]=0.f;

  auto issue=[&](int t){
    int st=t&3;
    long o=(long)t*32;
    uint32_t dA=smA0+(uint32_t)st*20480u+offT, dB=smB0+(uint32_t)st*20480u+offT;
    cpa16(dA,       Ah+abase+o); cpa16(dA+16,       Ah+abase+o+8);
    cpa16(dA+10240, Al+abase+o); cpa16(dA+10240+16, Al+abase+o+8);
    cpa16(dB,       Bh+bbase+o); cpa16(dB+16,       Bh+bbase+o+8);
    cpa16(dB+10240, Bl+bbase+o); cpa16(dB+10240+16, Bl+bbase+o+8);
  };

  issue(0); cpacommit();
  issue(1); cpacommit();
  issue(2); cpacommit();

#pragma unroll 1
  for(int t=0;t<256;t++){
    cpawait2();
    __syncthreads();
    if(t+3<256) issue(t+3);
    cpacommit();                      // one group per iter keeps wait_group<2> == "stage t ready"
    const int st=t&3;
#pragma unroll
    for(int ks=0;ks<2;ks++){
      const int ksub=ks*16;
      uint32_t af[2][2][4];
#pragma unroll
      for(int mt=0;mt<2;mt++)
#pragma unroll
        for(int s=0;s<2;s++){
          int row=wm*32+mt*16+(lane&15);
          int ce=ksub+(lane>>4)*8;
          ldm4(af[mt][s], smA0 + (uint32_t)(((st*2+s)*128+row)*40+ce)*2u);
        }
      uint32_t bfm[4][2][4];
#pragma unroll
      for(int p2=0;p2<4;p2++)
#pragma unroll
        for(int s=0;s<2;s++){
          int g=lane>>3, i=lane&7;
          int row=wn*64+p2*16+((g>>1)<<3)+i;
          int ce=ksub+((g&1)<<3);
          ldm4(bfm[p2][s], smB0 + (uint32_t)(((st*2+s)*128+row)*40+ce)*2u);
        }
#pragma unroll
      for(int mt=0;mt<2;mt++)
#pragma unroll
        for(int nt=0;nt<8;nt++){
          uint32_t b0h=bfm[nt>>1][0][(nt&1)*2], b1h=bfm[nt>>1][0][(nt&1)*2+1];
          uint32_t b0l=bfm[nt>>1][1][(nt&1)*2], b1l=bfm[nt>>1][1][(nt&1)*2+1];
          mma16816(acc[mt][nt], af[mt][0], b0h, b1h);
          mma16816(acc[mt][nt], af[mt][0], b0l, b1l);
          mma16816(acc[mt][nt], af[mt][1], b0h, b1h);
        }
    }
  }

  // epilogue: bias + relu -> padded b2; c2/c3 belong to row m+8 (stride 8*68*68)
#pragma unroll
  for(int mt=0;mt<2;mt++){
    int m=m0+wm*32+mt*16+(lane>>2);
    float bv0=bias[m], bv1=bias[m+8];
#pragma unroll
    for(int nt=0;nt<8;nt++){
      float* c=acc[mt][nt];
      int nI=n0+wn*64+nt*8+(lane&3)*2;
      int b=nI>>12, p=nI&4095, oy=p>>6, ox=p&63;
      long rb=((long)(b*256+m)*68+oy+2)*68+ox+2;
      float2 v0; v0.x=fmaxf(c[0]+bv0,0.f); v0.y=fmaxf(c[1]+bv0,0.f);
      float2 v1; v1.x=fmaxf(c[2]+bv1,0.f); v1.y=fmaxf(c[3]+bv1,0.f);
      *(float2*)(out+rb)=v0;
      *(float2*)(out+rb+8*68*68)=v1;
    }
  }
}

// ============ gather conv (residual layers + h3) ============
template<int IC,int IH,int IW,int OC,int OH,int OW,
         int KH,int KW,int SH,int SW,int PH,int PW,int NSPLIT,bool RELU_IN>
__global__ void __launch_bounds__(256,2)
conv_gemm(const float* __restrict__ W, const float* __restrict__ X,
          const float* __restrict__ bias, float* __restrict__ out)
{
  constexpr int BM=128, BN=128, BK=8;
  constexpr int Ktot=IC*KH*KW, Ksp=Ktot/NSPLIT, NT=Ksp/BK;
  constexpr int OHW=OH*OW, Ntot=8*OHW;
  __shared__ float As[2][BK][BM];
  __shared__ float Bs[2][BK][BN];
  const int tid=threadIdx.x;
  const int n0=blockIdx.x*BN, m0=blockIdx.y*BM, kb0=blockIdx.z*Ksp;
  const int am=tid>>1, ak=(tid&1)*4;
  const float* Aptr = W + (m0+am)*Ktot + kb0 + ak;
  const int gk=tid>>5, gn=(tid&31)*4;
  int nbase[4], iy0[4], ix0[4];
#pragma unroll
  for(int j=0;j<4;j++){
    int n=n0+gn+j; int b=n/OHW, p=n-b*OHW;
    int oy=p/OW, ox=p-oy*OW;
    iy0[j]=oy*SH-PH; ix0[j]=ox*SW-PW;
    nbase[j]=b*(IC*IH*IW);
  }
  const int tx4=(tid&15)*4, ty4=(tid>>4)*4;
  unsigned long long acc[8][4];
#pragma unroll
  for(int i=0;i<8;i++){
#pragma unroll
    for(int p=0;p<4;p++) acc[i][p]=0ull; }
  float4 areg=*(const float4*)Aptr;
  float br[4];
  {
    int kg=kb0+gk, ic=kg/(KH*KW), r=kg-ic*(KH*KW), ky=r/KW, kx=r-ky*KW;
#pragma unroll
    for(int j=0;j<4;j++){
      int iy=iy0[j]+ky, ix=ix0[j]+kx; float v=0.f;
      if((unsigned)iy<(unsigned)IH && (unsigned)ix<(unsigned)IW)
        v=X[nbase[j]+ic*(IH*IW)+iy*IW+ix];
      if(RELU_IN) v=fmaxf(v,0.f);
      br[j]=v;
    }
  }
  As[0][ak+0][am]=areg.x; As[0][ak+1][am]=areg.y;
  As[0][ak+2][am]=areg.z; As[0][ak+3][am]=areg.w;
  *(float4*)&Bs[0][gk][gn]=make_float4(br[0],br[1],br[2],br[3]);
  __syncthreads();
#pragma unroll 1
  for(int t=0;t<NT;t++){
    const int cur=t&1, nxt=cur^1; const bool more=(t+1<NT);
    float4 aN; float bN[4];
    if(more){
      aN=*(const float4*)(Aptr+(t+1)*BK);
      int kg=kb0+(t+1)*BK+gk, ic=kg/(KH*KW), r=kg-ic*(KH*KW), ky=r/KW, kx=r-ky*KW;
#pragma unroll
      for(int j=0;j<4;j++){
        int iy=iy0[j]+ky, ix=ix0[j]+kx; float v=0.f;
        if((unsigned)iy<(unsigned)IH && (unsigned)ix<(unsigned)IW)
          v=X[nbase[j]+ic*(IH*IW)+iy*IW+ix];
        if(RELU_IN) v=fmaxf(v,0.f);
        bN[j]=v;
      }
    }
#pragma unroll
    for(int k=0;k<BK;k++){
      float4 a0=*(const float4*)&As[cur][k][ty4];
      float4 a1=*(const float4*)&As[cur][k][ty4+64];
      ulonglong2 B0=*(const ulonglong2*)&Bs[cur][k][tx4];
      ulonglong2 B1=*(const ulonglong2*)&Bs[cur][k][tx4+64];
      float av[8]={a0.x,a0.y,a0.z,a0.w,a1.x,a1.y,a1.z,a1.w};
#pragma unroll
      for(int i=0;i<8;i++){
        unsigned long long ad=fdup(av[i]);
        ffma2(acc[i][0],ad,B0.x); ffma2(acc[i][1],ad,B0.y);
        ffma2(acc[i][2],ad,B1.x); ffma2(acc[i][3],ad,B1.y);
      }
    }
    if(more){
      As[nxt][ak+0][am]=aN.x; As[nxt][ak+1][am]=aN.y;
      As[nxt][ak+2][am]=aN.z; As[nxt][ak+3][am]=aN.w;
      *(float4*)&Bs[nxt][gk][gn]=make_float4(bN[0],bN[1],bN[2],bN[3]);
    }
    __syncthreads();
  }
#pragma unroll
  for(int i=0;i<8;i++){
    int m=m0+ty4+((i<4)?i:(60+i));
    float* pp = out + ((long)blockIdx.z*OC+m)*Ntot + n0;
    float2 v0=funpack(acc[i][0]), v1=funpack(acc[i][1]);
    float2 v2=funpack(acc[i][2]), v3=funpack(acc[i][3]);
    *(float4*)(pp+tx4)    = make_float4(v0.x,v0.y,v1.x,v1.y);
    *(float4*)(pp+tx4+64) = make_float4(v2.x,v2.y,v3.x,v3.y);
  }
}

__global__ void epilogue_k(const float* __restrict__ part, const float* __restrict__ bias,
                           const float* __restrict__ add, float* __restrict__ out,
                           int M, int N, int OHW, int nsplit, int relu, int OWd, int pad)
{
  int gid=blockIdx.x*256+threadIdx.x;
  if(gid>=M*N) return;
  int m=gid/N, n=gid-m*N;
  float s=0.f;
  for(int sp=0; sp<nsplit; sp++) s += part[((long)sp*M+m)*N+n];
  if(bias) s += bias[m];
  int b=n/OHW, p=n-b*OHW;
  if(add) s += add[((long)b*M+m)*OHW+p];
  if(relu) s=fmaxf(s,0.f);
  long oa;
  if(pad){
    int oy=p/OWd, ox=p-oy*OWd, OHd=OHW/OWd;
    oa=((long)((b*M+m)*(OHd+4)+(oy+2)))*(OWd+4)+ox+2;
  } else oa=((long)b*M+m)*OHW+p;
  out[oa]=s;
}

__global__ void transpose_emb_k(const float* __restrict__ emb, float* __restrict__ embT){
  int gid=blockIdx.x*256+threadIdx.x;
  embT[gid]=emb[(gid&511)*256+(gid>>9)];
}
__global__ void emb_normsT_k(const float* __restrict__ embT, float* __restrict__ se){
  int c=blockIdx.x*256+threadIdx.x; float s=0.f;
  for(int d=0; d<256; d++){ float v=embT[d*512+c]; s=fmaf(v,v,s); }
  se[c]=s;
}
__global__ void vq_rows_k(const float* __restrict__ lat, const float* __restrict__ embT,
                          const float* __restrict__ emb, const float* __restrict__ se,
                          int* __restrict__ idxo, float* __restrict__ sqo)
{
  __shared__ float sl[256]; __shared__ float sval[256]; __shared__ int sidx[256];
  int r=blockIdx.x, t=threadIdx.x, b=r>>6, p=r&63;
  sl[t]=lat[((b<<8)+t)*64+p];
  __syncthreads();
  float fn=0.f;
  for(int k=0;k<256;k++) fn=fmaf(sl[k],sl[k],fn);
  float d0=0.f,d1=0.f;
  for(int k=0;k<256;k++){
    float v=sl[k];
    d0=fmaf(embT[k*512+t],v,d0); d1=fmaf(embT[k*512+t+256],v,d1);
  }
  float dist0=fn+se[t]-2.f*d0, dist1=fn+se[t+256]-2.f*d1;
  float best; int bi;
  if(dist1<dist0){best=dist1; bi=t+256;} else {best=dist0; bi=t;}
  sval[t]=best; sidx[t]=bi;
  __syncthreads();
  for(int s=128;s>0;s>>=1){
    if(t<s){
      float v2=sval[t+s]; int i2=sidx[t+s];
      if(v2<sval[t] || (v2==sval[t] && i2<sidx[t])){ sval[t]=v2; sidx[t]=i2; }
    }
    __syncthreads();
  }
  int w=sidx[0];
  if(t==0) idxo[r]=w;
  __syncthreads();
  float diff=emb[w*256+t]-sl[t];
  sval[t]=diff*diff;
  __syncthreads();
  for(int s=128;s>0;s>>=1){
    if(t<s) sval[t]+=sval[t+s];
    __syncthreads();
  }
  if(t==0) sqo[r]=sval[0];
}
__global__ void write_quant_k(const int* __restrict__ idx, const float* __restrict__ emb,
                              float* __restrict__ out){
  int gid=blockIdx.x*256+threadIdx.x;
  out[gid]=emb[idx[((gid>>14)<<6)+(gid&63)]*256+((gid>>6)&255)];
}
__global__ void finalize_k(const int* __restrict__ idx, const float* __restrict__ sq,
                           float* __restrict__ out2){
  __shared__ float sh[512]; __shared__ float ss[512];
  int t=threadIdx.x; int cnt=0;
  for(int r=0;r<512;r++) cnt += (idx[r]==t)?1:0;
  float pr=(float)cnt*(1.f/512.f);
  sh[t]=-pr*logf(pr+1e-10f); ss[t]=sq[t];
  __syncthreads();
  for(int s=256;s>0;s>>=1){
    if(t<s){ sh[t]+=sh[t+s]; ss[t]+=ss[t+s]; }
    __syncthreads();
  }
  if(t==0){ out2[0]=2.f*ss[0]*(1.f/131072.f); out2[1]=expf(sh[0]); }
}

template<int IC,int IH,int IW,int OC,int OH,int OW,int KH,int KW,
         int SH,int SW,int PH,int PW,int NSPLIT,bool RIN>
static void launch_old(const float* W, const float* X, const float* bias, float* out){
  dim3 g((8*OH*OW)/128, OC/128, NSPLIT);
  conv_gemm<IC,IH,IW,OC,OH,OW,KH,KW,SH,SW,PH,PW,NSPLIT,RIN><<<g,256>>>(W,X,bias,out);
}

extern "C" void kernel_launch(void* const* d_in, const int* in_sizes, int n_in,
                              void* d_out, int out_size)
{
  const float* x     = (const float*)d_in[0];
  const float* w_in  = (const float*)d_in[1];
  const float* b_in  = (const float*)d_in[2];
  const float* w_h1  = (const float*)d_in[3];
  const float* b_h1  = (const float*)d_in[4];
  const float* w_h2  = (const float*)d_in[5];
  const float* b_h2  = (const float*)d_in[6];
  const float* w_h3  = (const float*)d_in[7];
  const float* b_h3  = (const float*)d_in[8];
  const float* r0_w1 = (const float*)d_in[9];
  const float* r0_w2 = (const float*)d_in[10];
  const float* r1_w1 = (const float*)d_in[11];
  const float* r1_w2 = (const float*)d_in[12];
  const float* emb   = (const float*)d_in[13];
  float* out = (float*)d_out;

  float *b1,*b2,*b3,*b4,*b5,*b6,*tr,*pp,*cS,*eT,*se,*sq; int* gi;
  __nv_bfloat16 *Ah,*Al,*Bh,*Bl;
  cudaGetSymbolAddress((void**)&b1,g_buf1);
  cudaGetSymbolAddress((void**)&b2,g_buf2);
  cudaGetSymbolAddress((void**)&b3,g_buf3);
  cudaGetSymbolAddress((void**)&b4,g_buf4);
  cudaGetSymbolAddress((void**)&b5,g_buf5);
  cudaGetSymbolAddress((void**)&b6,g_buf6);
  cudaGetSymbolAddress((void**)&tr,g_tres);
  cudaGetSymbolAddress((void**)&pp,g_part);
  cudaGetSymbolAddress((void**)&cS,g_colS);
  cudaGetSymbolAddress((void**)&eT,g_embT);
  cudaGetSymbolAddress((void**)&se,g_se);
  cudaGetSymbolAddress((void**)&sq,g_sqn);
  cudaGetSymbolAddress((void**)&gi,g_idx);
  cudaGetSymbolAddress((void**)&Ah,g_Ah);
  cudaGetSymbolAddress((void**)&Al,g_Al);
  cudaGetSymbolAddress((void**)&Bh,g_Bh);
  cudaGetSymbolAddress((void**)&Bl,g_Bl);

  cudaFuncSetAttribute(h1_mma_k, cudaFuncAttributeMaxDynamicSharedMemorySize, 163840);

  im2col0_k<<<2048,256>>>(x, cS);                                             // 0
  { dim3 g(4096,1,1); gemm_k<128,524288,48,1,2,256,256><<<g,256>>>(w_in, cS, b_in, b1); } // 1
  im2col1T_k<<<520,256>>>(b1, w_h1, Bh, Bl, Ah, Al);                          // 2
  h1_mma_k<<<dim3(256,2),256,163840>>>(Ah, Al, Bh, Bl, b_h1, b2);             // 3 PROFILED
  im2col2_k<<<128,256>>>(b2, cS);
  { dim3 g(16,2,8); gemm_k<256,2048,12544,8,1,0,0><<<g,256>>>(w_h2, cS, nullptr, pp); }
  epilogue_k<<<(256*2048+255)/256,256>>>(pp, b_h2, nullptr, b3, 256, 2048, 256, 8, 1, 16, 0);
  launch_old<256,16,16, 256,8,8, 3,3, 2,2, 1,1, 16,false>(w_h3, b3, nullptr, pp);
  epilogue_k<<<(256*512+255)/256,256>>>(pp, b_h3, nullptr, b4, 256, 512, 64, 16, 1, 8, 0);

  launch_old<256,8,8, 1024,8,8, 1,3, 1,1, 0,1, 8,false>(r0_w1, b4, nullptr, pp);
  epilogue_k<<<(1024*512+255)/256,256>>>(pp, nullptr, nullptr, tr, 1024, 512, 64, 8, 1, 8, 0);
  launch_old<1024,8,8, 256,8,8, 1,1, 1,1, 0,0, 8,false>(r0_w2, tr, nullptr, pp);
  epilogue_k<<<(256*512+255)/256,256>>>(pp, nullptr, b4, b5, 256, 512, 64, 8, 0, 8, 0);

  launch_old<256,8,8, 1024,8,8, 1,3, 1,1, 0,1, 8,true>(r1_w1, b5, nullptr, pp);
  epilogue_k<<<(1024*512+255)/256,256>>>(pp, nullptr, nullptr, tr, 1024, 512, 64, 8, 1, 8, 0);
  launch_old<1024,8,8, 256,8,8, 1,1, 1,1, 0,0, 8,false>(r1_w2, tr, nullptr, pp);
  epilogue_k<<<(256*512+255)/256,256>>>(pp, nullptr, b5, b6, 256, 512, 64, 8, 1, 8, 0);

  transpose_emb_k<<<512,256>>>(emb, eT);
  emb_normsT_k<<<2,256>>>(eT, se);
  vq_rows_k<<<512,256>>>(b6, eT, emb, se, gi, sq);
  write_quant_k<<<512,256>>>(gi, emb, out);
  finalize_k<<<1,512>>>(gi, sq, out + 131072);
}